// round 5
// baseline (speedup 1.0000x reference)
#include <cuda_runtime.h>

#define BLOCK 256
#define NROWS 262144
#define GRID (NROWS / (BLOCK * 2))

using ull = unsigned long long;

// ---------------- shared memory layout (floats) ----------------
// Packed pair-interleaved weights: (pair p, input j) at OFF + (p*K + j)*2,
// storing (W[2p][j], W[2p+1][j]) as consecutive floats (lo, hi of a b64).
constexpr int OFF_L1  = 0;                    // up_m_w1 folded: 32 pairs x 44
constexpr int OFF_L2  = OFF_L1 + 32 * 44 * 2; // up_m_w2: 32 pairs x 64
constexpr int OFF_L3  = OFF_L2 + 32 * 64 * 2; // up_m_w3: 36 pairs x 64
constexpr int OFF_F1  = OFF_L3 + 36 * 64 * 2; // fr_w1 folded: 32 x 44
constexpr int OFF_F2  = OFF_F1 + 32 * 44 * 2; // fr_w2: 32 x 64
constexpr int OFF_F3  = OFF_F2 + 32 * 64 * 2; // fr_w3: 4 x 64
constexpr int OFF_B1P = OFF_F3 + 4 * 64 * 2;  // biases (pair-packed order = linear)
constexpr int OFF_B2P = OFF_B1P + 64;
constexpr int OFF_B3P = OFF_B2P + 64;         // 72
constexpr int OFF_FB1P = OFF_B3P + 72;
constexpr int OFF_FB2P = OFF_FB1P + 64;
constexpr int OFF_FB3P = OFF_FB2P + 64;       // 8
constexpr int OFF_UH1W = OFF_FB3P + 8;        // 8x13
constexpr int OFF_UH1B = OFF_UH1W + 104;      // 8
constexpr int OFF_G1W  = OFF_UH1B + 8;        // 8x8
constexpr int OFF_G1B  = OFF_G1W + 64;        // 8
constexpr int OFF_G2W  = OFF_G1B + 8;         // 8
constexpr int OFF_G2B  = OFF_G2W + 8;         // 1 (pad 4)
constexpr int OFF_UZ1  = OFF_G2B + 4;         // 8x4
constexpr int OFF_UZ2S = OFF_UZ1 + 32;        // 8x8
constexpr int OFF_UZ2Z = OFF_UZ2S + 64;       // 8
constexpr int OFF_DG1W = OFF_UZ2Z + 8;        // 8x8
constexpr int OFF_DG1B = OFF_DG1W + 64;       // 8
constexpr int OFF_DG2W = OFF_DG1B + 8;        // 8
constexpr int OFF_DG2B = OFF_DG2W + 8;        // 1 (pad 4)
constexpr int OFF_DZ2S = OFF_DG2B + 4;        // 8x8
constexpr int OFF_DZ2Z = OFF_DZ2S + 64;       // 8
// activation scratch: 64 k-slots x float2(rowA,rowB) per thread, lane-interleaved
constexpr int OFF_SCR = OFF_DZ2Z + 8;         // = 19736 (16B aligned: 78944 bytes)
constexpr int SMEM_FLOATS = OFF_SCR + 64 * 2 * BLOCK;   // 52504 floats = 210016 B

// ---------------- f32x2 packed helpers ----------------
__device__ __forceinline__ ull pk2(float x) {
    ull r; unsigned xi = __float_as_uint(x);
    asm("mov.b64 %0, {%1, %1};" : "=l"(r) : "r"(xi));
    return r;
}
__device__ __forceinline__ ull f2fma(ull a, ull b, ull c) {
    ull d;
    asm("fma.rn.f32x2 %0, %1, %2, %3;" : "=l"(d) : "l"(a), "l"(b), "l"(c));
    return d;
}
__device__ __forceinline__ float2 up2(ull v) {
    unsigned lo, hi;
    asm("mov.b64 {%0, %1}, %2;" : "=r"(lo), "=r"(hi) : "l"(v));
    return make_float2(__uint_as_float(lo), __uint_as_float(hi));
}

// ---- layer: x in registers (both rows) -> relu -> scratch ----
template<int KHALF, int NPAIRS>
__device__ __forceinline__ void layer_r2s(const ulonglong2* __restrict__ W,
                                          const ull* __restrict__ Bp,
                                          const float* __restrict__ xA,
                                          const float* __restrict__ xB,
                                          float2* __restrict__ scrT)
{
#pragma unroll
    for (int c = 0; c < NPAIRS / 4; c++) {
        ull aA[4], aB[4];
#pragma unroll
        for (int p = 0; p < 4; p++) { ull b = Bp[c * 4 + p]; aA[p] = b; aB[p] = b; }
#pragma unroll
        for (int t = 0; t < KHALF; t++) {
            ull xaA = pk2(xA[2 * t]), xbA = pk2(xA[2 * t + 1]);
            ull xaB = pk2(xB[2 * t]), xbB = pk2(xB[2 * t + 1]);
#pragma unroll
            for (int p = 0; p < 4; p++) {
                ulonglong2 w = W[(c * 4 + p) * KHALF + t];
                aA[p] = f2fma(w.x, xaA, aA[p]); aA[p] = f2fma(w.y, xbA, aA[p]);
                aB[p] = f2fma(w.x, xaB, aB[p]); aB[p] = f2fma(w.y, xbB, aB[p]);
            }
        }
#pragma unroll
        for (int p = 0; p < 4; p++) {
            float2 rA = up2(aA[p]), rB = up2(aB[p]);
            scrT[(c * 8 + 2 * p) * BLOCK]     = make_float2(fmaxf(rA.x, 0.f), fmaxf(rB.x, 0.f));
            scrT[(c * 8 + 2 * p + 1) * BLOCK] = make_float2(fmaxf(rA.y, 0.f), fmaxf(rB.y, 0.f));
        }
    }
}

// ---- layer: x from scratch -> relu -> registers (both rows) ----
template<int KHALF, int NPAIRS>
__device__ __forceinline__ void layer_s2r(const ulonglong2* __restrict__ W,
                                          const ull* __restrict__ Bp,
                                          const float2* __restrict__ scrT,
                                          float* __restrict__ yA,
                                          float* __restrict__ yB)
{
#pragma unroll
    for (int c = 0; c < NPAIRS / 4; c++) {
        ull aA[4], aB[4];
#pragma unroll
        for (int p = 0; p < 4; p++) { ull b = Bp[c * 4 + p]; aA[p] = b; aB[p] = b; }
#pragma unroll
        for (int t = 0; t < KHALF; t++) {
            float2 x0 = scrT[(2 * t) * BLOCK];
            float2 x1 = scrT[(2 * t + 1) * BLOCK];
            ull xaA = pk2(x0.x), xaB = pk2(x0.y);
            ull xbA = pk2(x1.x), xbB = pk2(x1.y);
#pragma unroll
            for (int p = 0; p < 4; p++) {
                ulonglong2 w = W[(c * 4 + p) * KHALF + t];
                aA[p] = f2fma(w.x, xaA, aA[p]); aA[p] = f2fma(w.y, xbA, aA[p]);
                aB[p] = f2fma(w.x, xaB, aB[p]); aB[p] = f2fma(w.y, xbB, aB[p]);
            }
        }
#pragma unroll
        for (int p = 0; p < 4; p++) {
            float2 rA = up2(aA[p]), rB = up2(aB[p]);
            yA[c * 8 + 2 * p]     = fmaxf(rA.x, 0.f);
            yB[c * 8 + 2 * p]     = fmaxf(rB.x, 0.f);
            yA[c * 8 + 2 * p + 1] = fmaxf(rA.y, 0.f);
            yB[c * 8 + 2 * p + 1] = fmaxf(rB.y, 0.f);
        }
    }
}

__global__ void __launch_bounds__(BLOCK, 1) frame_gnn_kernel(
    const float* __restrict__ state,
    const float* __restrict__ up_Z1_w, const float* __restrict__ up_h1_w, const float* __restrict__ up_h1_b,
    const float* __restrict__ up_g1_w1, const float* __restrict__ up_g1_b1,
    const float* __restrict__ up_g1_w2, const float* __restrict__ up_g1_b2,
    const float* __restrict__ up_Z2_w,
    const float* __restrict__ up_m_w1, const float* __restrict__ up_m_b1,
    const float* __restrict__ up_m_w2, const float* __restrict__ up_m_b2,
    const float* __restrict__ up_m_w3, const float* __restrict__ up_m_b3,
    const float* __restrict__ dn_g1_w1, const float* __restrict__ dn_g1_b1,
    const float* __restrict__ dn_g1_w2, const float* __restrict__ dn_g1_b2,
    const float* __restrict__ dn_Z2_w,
    const float* __restrict__ fr_w1, const float* __restrict__ fr_b1,
    const float* __restrict__ fr_w2, const float* __restrict__ fr_b2,
    const float* __restrict__ fr_w3, const float* __restrict__ fr_b3,
    float* __restrict__ out)
{
    extern __shared__ float sm[];
    const int tid = threadIdx.x;

    // ---------------- stage + fold + pair-pack weights ----------------
    if (tid < 64) {
        const int k = tid;
        const int base1 = OFF_L1 + (k >> 1) * 88 + (k & 1);
        const int basef = OFF_F1 + (k >> 1) * 88 + (k & 1);
        int p = 0;
        for (int a = 0; a < 8; a++) {
            for (int b = a; b < 8; b++) {
                float w = up_m_w1[k * 88 + a * 8 + b];
                float f = fr_w1[k * 80 + a * 8 + b];
                if (a != b) {
                    w += up_m_w1[k * 88 + b * 8 + a];
                    f += fr_w1[k * 80 + b * 8 + a];
                }
                sm[base1 + p * 2] = w;
                sm[basef + p * 2] = f;
                p++;
            }
        }
        for (int j = 0; j < 8; j++) {
            sm[base1 + (36 + j) * 2] = up_m_w1[k * 88 + 64 + j];
            sm[basef + (36 + j) * 2] = fr_w1[k * 80 + 64 + j];
        }
    }
    for (int e = tid; e < 64 * 64; e += BLOCK) {
        const int k = e >> 6, j = e & 63;
        const int d = ((k >> 1) * 64 + j) * 2 + (k & 1);
        sm[OFF_L2 + d] = up_m_w2[e];
        sm[OFF_F2 + d] = fr_w2[e];
    }
    for (int e = tid; e < 72 * 64; e += BLOCK) {
        const int k = e >> 6, j = e & 63;
        sm[OFF_L3 + ((k >> 1) * 64 + j) * 2 + (k & 1)] = up_m_w3[e];
    }
    for (int e = tid; e < 8 * 64; e += BLOCK) {
        const int k = e >> 6, j = e & 63;
        sm[OFF_F3 + ((k >> 1) * 64 + j) * 2 + (k & 1)] = fr_w3[e];
    }
    for (int i = tid; i < 64; i += BLOCK) {
        sm[OFF_B1P + i] = up_m_b1[i]; sm[OFF_B2P + i] = up_m_b2[i];
        sm[OFF_FB1P + i] = fr_b1[i];  sm[OFF_FB2P + i] = fr_b2[i];
    }
    for (int i = tid; i < 72; i += BLOCK) sm[OFF_B3P + i] = up_m_b3[i];
    for (int i = tid; i < 104; i += BLOCK) sm[OFF_UH1W + i] = up_h1_w[i];
    for (int i = tid; i < 32; i += BLOCK) sm[OFF_UZ1 + i] = up_Z1_w[i];
    for (int i = tid; i < 64; i += BLOCK) {
        const int k = i >> 3, j = i & 7;
        sm[OFF_G1W + i]  = up_g1_w1[k * 24 + j];
        sm[OFF_DG1W + i] = dn_g1_w1[k * 16 + j];
        sm[OFF_UZ2S + i] = up_Z2_w[k * 25 + j];
        sm[OFF_DZ2S + i] = dn_Z2_w[k * 17 + j];
    }
    if (tid < 8) {
        sm[OFF_FB3P + tid] = fr_b3[tid];
        sm[OFF_UH1B + tid] = up_h1_b[tid];
        sm[OFF_G1B + tid]  = up_g1_b1[tid];
        sm[OFF_G2W + tid]  = up_g1_w2[tid];
        sm[OFF_UZ2Z + tid] = up_Z2_w[tid * 25 + 24];
        sm[OFF_DG1B + tid] = dn_g1_b1[tid];
        sm[OFF_DG2W + tid] = dn_g1_w2[tid];
        sm[OFF_DZ2Z + tid] = dn_Z2_w[tid * 17 + 16];
    }
    if (tid == 0) { sm[OFF_G2B] = up_g1_b2[0]; sm[OFF_DG2B] = dn_g1_b2[0]; }
    __syncthreads();

    const ulonglong2* W1 = reinterpret_cast<const ulonglong2*>(sm + OFF_L1);
    const ulonglong2* W2 = reinterpret_cast<const ulonglong2*>(sm + OFF_L2);
    const ulonglong2* W3 = reinterpret_cast<const ulonglong2*>(sm + OFF_L3);
    const ulonglong2* G1 = reinterpret_cast<const ulonglong2*>(sm + OFF_F1);
    const ulonglong2* G2 = reinterpret_cast<const ulonglong2*>(sm + OFF_F2);
    const ulonglong2* G3 = reinterpret_cast<const ulonglong2*>(sm + OFF_F3);
    const ull* B1P = reinterpret_cast<const ull*>(sm + OFF_B1P);
    const ull* B2P = reinterpret_cast<const ull*>(sm + OFF_B2P);
    const ull* B3P = reinterpret_cast<const ull*>(sm + OFF_B3P);
    const ull* FB1P = reinterpret_cast<const ull*>(sm + OFF_FB1P);
    const ull* FB2P = reinterpret_cast<const ull*>(sm + OFF_FB2P);
    const ull* FB3P = reinterpret_cast<const ull*>(sm + OFF_FB3P);
    float2* scrT = reinterpret_cast<float2*>(sm + OFF_SCR) + tid;

    // ---------------- per-thread: 2 rows ----------------
    const int rA = blockIdx.x * (BLOCK * 2) + tid;
    const float* sR[2] = { state + (size_t)rA * 25, state + (size_t)(rA + BLOCK) * 25 };
    float* oR[2] = { out + (size_t)rA * 25, out + (size_t)(rA + BLOCK) * 25 };

    float xv[2][44];
    float Zm0[2][8], Zm1[2][8], Zm2[2][8];
    float invFn[2];

    // ---- front: h0 -> hm8 -> gs -> Zm -> gram -> xv (per row) ----
#pragma unroll
    for (int r = 0; r < 2; r++) {
        const float* s = sR[r];
        float* o = oR[r];
        float h0[13];
#pragma unroll
        for (int i = 0; i < 4; i++) { float v = s[i]; h0[i] = v; o[i] = v; }
#pragma unroll
        for (int i = 0; i < 9; i++) { float v = s[16 + i]; h0[4 + i] = v; o[16 + i] = v; }

        float hm8[8];
#pragma unroll
        for (int k = 0; k < 8; k++) {
            float a = sm[OFF_UH1B + k];
#pragma unroll
            for (int i = 0; i < 13; i++) a += h0[i] * sm[OFF_UH1W + k * 13 + i];
            hm8[k] = fmaxf(a, 0.f);
        }
        float gs = sm[OFF_G2B];
#pragma unroll
        for (int k = 0; k < 8; k++) {
            float a = sm[OFF_G1B + k];
#pragma unroll
            for (int i = 0; i < 8; i++) a += hm8[i] * sm[OFF_G1W + k * 8 + i];
            gs += fmaxf(a, 0.f) * sm[OFF_G2W + k];
        }
        float Z0x[4], Z0y[4], Z0z[4];
#pragma unroll
        for (int j = 0; j < 4; j++) { Z0x[j] = s[4 + 3 * j]; Z0y[j] = s[5 + 3 * j]; Z0z[j] = s[6 + 3 * j]; }
        float Zu0[8], Zu1[8], Zu2[8];
#pragma unroll
        for (int k = 0; k < 8; k++) {
            float a0 = 0.f, a1 = 0.f, a2 = 0.f;
#pragma unroll
            for (int j = 0; j < 4; j++) {
                float w = sm[OFF_UZ1 + k * 4 + j];
                a0 += Z0x[j] * w; a1 += Z0y[j] * w; a2 += Z0z[j] * w;
            }
            Zu0[k] = a0; Zu1[k] = a1; Zu2[k] = a2;
        }
#pragma unroll
        for (int k = 0; k < 8; k++) {
            float a0 = 0.f, a1 = 0.f, a2 = 0.f;
#pragma unroll
            for (int m = 0; m < 8; m++) {
                float w = sm[OFF_UZ2S + k * 8 + m];
                a0 += Zu0[m] * w; a1 += Zu1[m] * w; a2 += Zu2[m] * w;
            }
            a2 += gs * sm[OFF_UZ2Z + k];
            Zm0[r][k] = a0; Zm1[r][k] = a1; Zm2[r][k] = a2;
        }
        float nrm = 0.f;
        {
            int p = 0;
#pragma unroll
            for (int a = 0; a < 8; a++)
#pragma unroll
                for (int b = a; b < 8; b++) {
                    float v = Zm0[r][a] * Zm0[r][b] + Zm1[r][a] * Zm1[r][b] + Zm2[r][a] * Zm2[r][b];
                    xv[r][p] = v;
                    nrm += (a == b) ? v * v : 2.f * v * v;
                    p++;
                }
        }
#pragma unroll
        for (int j = 0; j < 8; j++) xv[r][36 + j] = hm8[j];
        invFn[r] = 1.f / (sqrtf(nrm) + 1.f);
    }

    // ---- up_m L1: xv(regs) -> t1(scratch) ----
    layer_r2s<22, 32>(W1, B1P, xv[0], xv[1], scrT);
    // ---- up_m L2: t1(scratch) -> t2(regs) ----
    float t2A[64], t2B[64];
    layer_s2r<32, 32>(W2, B2P, scrT, t2A, t2B);
    // copy t2 -> scratch (t1 dead), free regs for L3
#pragma unroll
    for (int k = 0; k < 64; k++) scrT[k * BLOCK] = make_float2(t2A[k], t2B[k]);

    // ---- up_m L3: t2(scratch), fused consumption ----
    float uZ0[2][8], uZ1[2][8], uZ2[2][8], hm2[2][8];
#pragma unroll
    for (int r = 0; r < 2; r++)
#pragma unroll
        for (int k = 0; k < 8; k++) { uZ0[r][k] = 0.f; uZ1[r][k] = 0.f; uZ2[r][k] = 0.f; }
#pragma unroll
    for (int c = 0; c < 9; c++) {
        ull aA[4], aB[4];
#pragma unroll
        for (int p = 0; p < 4; p++) { ull b = B3P[c * 4 + p]; aA[p] = b; aB[p] = b; }
#pragma unroll
        for (int t = 0; t < 32; t++) {
            float2 x0 = scrT[(2 * t) * BLOCK];
            float2 x1 = scrT[(2 * t + 1) * BLOCK];
            ull xaA = pk2(x0.x), xaB = pk2(x0.y);
            ull xbA = pk2(x1.x), xbB = pk2(x1.y);
#pragma unroll
            for (int p = 0; p < 4; p++) {
                ulonglong2 w = W3[(c * 4 + p) * 32 + t];
                aA[p] = f2fma(w.x, xaA, aA[p]); aA[p] = f2fma(w.y, xbA, aA[p]);
                aB[p] = f2fma(w.x, xaB, aB[p]); aB[p] = f2fma(w.y, xbB, aB[p]);
            }
        }
        if (c < 8) {
            // chunk c = row j=c of M: outputs j*8 + (0..7)
#pragma unroll
            for (int p = 0; p < 4; p++) {
                float2 mA = up2(aA[p]), mB = up2(aB[p]);
                const int k0 = 2 * p, k1 = 2 * p + 1;
                {
                    const float m0 = mA.x * invFn[0], m1 = mA.y * invFn[0];
                    uZ0[0][k0] += Zm0[0][c] * m0; uZ1[0][k0] += Zm1[0][c] * m0; uZ2[0][k0] += Zm2[0][c] * m0;
                    uZ0[0][k1] += Zm0[0][c] * m1; uZ1[0][k1] += Zm1[0][c] * m1; uZ2[0][k1] += Zm2[0][c] * m1;
                }
                {
                    const float m0 = mB.x * invFn[1], m1 = mB.y * invFn[1];
                    uZ0[1][k0] += Zm0[1][c] * m0; uZ1[1][k0] += Zm1[1][c] * m0; uZ2[1][k0] += Zm2[1][c] * m0;
                    uZ0[1][k1] += Zm0[1][c] * m1; uZ1[1][k1] += Zm1[1][c] * m1; uZ2[1][k1] += Zm2[1][c] * m1;
                }
            }
        } else {
#pragma unroll
            for (int p = 0; p < 4; p++) {
                float2 mA = up2(aA[p]), mB = up2(aB[p]);
                hm2[0][2 * p] = fmaxf(mA.x * invFn[0], 0.f);
                hm2[0][2 * p + 1] = fmaxf(mA.y * invFn[0], 0.f);
                hm2[1][2 * p] = fmaxf(mB.x * invFn[1], 0.f);
                hm2[1][2 * p + 1] = fmaxf(mB.y * invFn[1], 0.f);
            }
        }
    }

    // ---- gs2, Y, second gram -> xv, keep Y0,Y1 (per row) ----
    float Yx[2][8], Yy[2][8];
    float invFn2[2];
#pragma unroll
    for (int r = 0; r < 2; r++) {
        float gs2 = sm[OFF_DG2B];
#pragma unroll
        for (int k = 0; k < 8; k++) {
            float a = sm[OFF_DG1B + k];
#pragma unroll
            for (int i = 0; i < 8; i++) a += hm2[r][i] * sm[OFF_DG1W + k * 8 + i];
            gs2 += fmaxf(a, 0.f) * sm[OFF_DG2W + k];
        }
        float Y2l[8];
#pragma unroll
        for (int k = 0; k < 8; k++) {
            float a0 = 0.f, a1 = 0.f, a2 = 0.f;
#pragma unroll
            for (int j = 0; j < 8; j++) {
                float w = sm[OFF_DZ2S + k * 8 + j];
                a0 += uZ0[r][j] * w; a1 += uZ1[r][j] * w; a2 += uZ2[r][j] * w;
            }
            a2 += gs2 * sm[OFF_DZ2Z + k];
            Yx[r][k] = a0; Yy[r][k] = a1; Y2l[k] = a2;
        }
        float nrm2 = 0.f;
        {
            int p = 0;
#pragma unroll
            for (int a = 0; a < 8; a++)
#pragma unroll
                for (int b = a; b < 8; b++) {
                    float v = Yx[r][a] * Yx[r][b] + Yy[r][a] * Yy[r][b] + Y2l[a] * Y2l[b];
                    xv[r][p] = v;
                    nrm2 += (a == b) ? v * v : 2.f * v * v;
                    p++;
                }
        }
#pragma unroll
        for (int j = 0; j < 8; j++) xv[r][36 + j] = hm2[r][j];
        invFn2[r] = 1.f / (sqrtf(nrm2) + 1.f);
    }

    // ---- fr L1: xv(regs) -> f1(scratch) ----
    layer_r2s<22, 32>(G1, FB1P, xv[0], xv[1], scrT);
    // ---- fr L2: f1(scratch) -> f2(regs) ----
    float f2A[64], f2B[64];
    layer_s2r<32, 32>(G2, FB2P, scrT, f2A, f2B);
    // ---- fr L3: f2(regs) -> frv ----
    float frv[2][8];
    {
        ull aA[4], aB[4];
#pragma unroll
        for (int p = 0; p < 4; p++) { ull b = FB3P[p]; aA[p] = b; aB[p] = b; }
#pragma unroll
        for (int t = 0; t < 32; t++) {
            ull xaA = pk2(f2A[2 * t]), xbA = pk2(f2A[2 * t + 1]);
            ull xaB = pk2(f2B[2 * t]), xbB = pk2(f2B[2 * t + 1]);
#pragma unroll
            for (int p = 0; p < 4; p++) {
                ulonglong2 w = G3[p * 32 + t];
                aA[p] = f2fma(w.x, xaA, aA[p]); aA[p] = f2fma(w.y, xbA, aA[p]);
                aB[p] = f2fma(w.x, xaB, aB[p]); aB[p] = f2fma(w.y, xbB, aB[p]);
            }
        }
#pragma unroll
        for (int p = 0; p < 4; p++) {
            float2 rAv = up2(aA[p]), rBv = up2(aB[p]);
            frv[0][2 * p] = rAv.x * invFn2[0]; frv[0][2 * p + 1] = rAv.y * invFn2[0];
            frv[1][2 * p] = rBv.x * invFn2[1]; frv[1][2 * p + 1] = rBv.y * invFn2[1];
        }
    }

    // ---- frame + rotation + writeback (per row) ----
#pragma unroll
    for (int r = 0; r < 2; r++) {
        float fx = 0.f, fy = 0.f;
#pragma unroll
        for (int k = 0; k < 8; k++) { fx += Yx[r][k] * frv[r][k]; fy += Yy[r][k] * frv[r][k]; }
        const float n = sqrtf(fx * fx + fy * fy) + 1e-6f;
        const float u1x = fx / n, u1y = fy / n;
        const float* s = sR[r];
        float* o = oR[r];
#pragma unroll
        for (int j = 0; j < 4; j++) {
            const float zx = __ldg(&s[4 + 3 * j]);
            const float zy = __ldg(&s[5 + 3 * j]);
            const float zz = __ldg(&s[6 + 3 * j]);
            o[4 + 3 * j]     = u1x * zx + u1y * zy;
            o[4 + 3 * j + 1] = -u1y * zx + u1x * zy;
            o[4 + 3 * j + 2] = zz;
        }
    }
}

extern "C" void kernel_launch(void* const* d_in, const int* in_sizes, int n_in,
                              void* d_out, int out_size) {
    (void)in_sizes; (void)n_in; (void)out_size;
    const size_t smem_bytes = SMEM_FLOATS * sizeof(float);
    cudaFuncSetAttribute(frame_gnn_kernel, cudaFuncAttributeMaxDynamicSharedMemorySize,
                         (int)smem_bytes);
    frame_gnn_kernel<<<GRID, BLOCK, smem_bytes>>>(
        (const float*)d_in[0],
        (const float*)d_in[1], (const float*)d_in[2], (const float*)d_in[3],
        (const float*)d_in[4], (const float*)d_in[5], (const float*)d_in[6], (const float*)d_in[7],
        (const float*)d_in[8],
        (const float*)d_in[9], (const float*)d_in[10], (const float*)d_in[11], (const float*)d_in[12],
        (const float*)d_in[13], (const float*)d_in[14],
        (const float*)d_in[15], (const float*)d_in[16], (const float*)d_in[17], (const float*)d_in[18],
        (const float*)d_in[19],
        (const float*)d_in[20], (const float*)d_in[21], (const float*)d_in[22], (const float*)d_in[23],
        (const float*)d_in[24], (const float*)d_in[25],
        (float*)d_out);
}

// round 6
// speedup vs baseline: 1.2449x; 1.2449x over previous
#include <cuda_runtime.h>

#define BLOCK 192
#define NROWS 262144
#define GRID ((NROWS + BLOCK - 1) / BLOCK)

using ull = unsigned long long;

// ---------------- shared memory layout (floats) ----------------
// Packed pair-interleaved weights: (pair p, input j) at OFF + (p*K + j)*2,
// storing (W[2p][j], W[2p+1][j]) as consecutive floats (lo, hi of a b64).
constexpr int OFF_L1  = 0;                    // up_m_w1 folded: 32 pairs x 44
constexpr int OFF_L2  = OFF_L1 + 32 * 44 * 2; // up_m_w2: 32 pairs x 64
constexpr int OFF_L3  = OFF_L2 + 32 * 64 * 2; // up_m_w3: 36 pairs x 64
constexpr int OFF_F1  = OFF_L3 + 36 * 64 * 2; // fr_w1 folded: 32 x 44
constexpr int OFF_F2  = OFF_F1 + 32 * 44 * 2; // fr_w2: 32 x 64
constexpr int OFF_F3  = OFF_F2 + 32 * 64 * 2; // fr_w3: 4 x 64
constexpr int OFF_B1P = OFF_F3 + 4 * 64 * 2;  // biases (pair-packed order = linear)
constexpr int OFF_B2P = OFF_B1P + 64;
constexpr int OFF_B3P = OFF_B2P + 64;         // 72
constexpr int OFF_FB1P = OFF_B3P + 72;
constexpr int OFF_FB2P = OFF_FB1P + 64;
constexpr int OFF_FB3P = OFF_FB2P + 64;       // 8
constexpr int OFF_UH1W = OFF_FB3P + 8;        // 8x13
constexpr int OFF_UH1B = OFF_UH1W + 104;      // 8
constexpr int OFF_G1W  = OFF_UH1B + 8;        // 8x8
constexpr int OFF_G1B  = OFF_G1W + 64;        // 8
constexpr int OFF_G2W  = OFF_G1B + 8;         // 8
constexpr int OFF_G2B  = OFF_G2W + 8;         // 1 (pad 4)
constexpr int OFF_UZ1  = OFF_G2B + 4;         // 8x4
constexpr int OFF_UZ2S = OFF_UZ1 + 32;        // 8x8
constexpr int OFF_UZ2Z = OFF_UZ2S + 64;       // 8
constexpr int OFF_DG1W = OFF_UZ2Z + 8;        // 8x8
constexpr int OFF_DG1B = OFF_DG1W + 64;       // 8
constexpr int OFF_DG2W = OFF_DG1B + 8;        // 8
constexpr int OFF_DG2B = OFF_DG2W + 8;        // 1 (pad 4)
constexpr int OFF_DZ2S = OFF_DG2B + 4;        // 8x8
constexpr int OFF_DZ2Z = OFF_DZ2S + 64;       // 8
// per-thread scratch: 24 rows x BLOCK (Zm0,Zm1,Zm2; later Y0,Y1)
constexpr int OFF_ZM = OFF_DZ2Z + 8;
constexpr int SMEM_FLOATS = OFF_ZM + 24 * BLOCK;

// ---------------- f32x2 packed helpers ----------------
__device__ __forceinline__ ull pk2(float x) {
    ull r; unsigned xi = __float_as_uint(x);
    asm("mov.b64 %0, {%1, %1};" : "=l"(r) : "r"(xi));
    return r;
}
__device__ __forceinline__ ull f2fma(ull a, ull b, ull c) {
    ull d;
    asm("fma.rn.f32x2 %0, %1, %2, %3;" : "=l"(d) : "l"(a), "l"(b), "l"(c));
    return d;
}
__device__ __forceinline__ float2 up2(ull v) {
    unsigned lo, hi;
    asm("mov.b64 {%0, %1}, %2;" : "=r"(lo), "=r"(hi) : "l"(v));
    return make_float2(__uint_as_float(lo), __uint_as_float(hi));
}

// 8 output-pairs over KHALF b64-steps. No manual prefetch: with ~40 spare
// registers (170-reg budget) ptxas hoists the LDS.128s itself.
template<int KHALF>
__device__ __forceinline__ void chunk8(const ulonglong2* __restrict__ Wb,
                                       const float* __restrict__ x,
                                       ull acc[8])
{
#pragma unroll
    for (int t = 0; t < KHALF; t++) {
        ull xa = pk2(x[2 * t]), xb = pk2(x[2 * t + 1]);
#pragma unroll
        for (int p = 0; p < 8; p++) {
            ulonglong2 w = Wb[p * KHALF + t];
            acc[p] = f2fma(w.x, xa, acc[p]);
            acc[p] = f2fma(w.y, xb, acc[p]);
        }
    }
}

template<int KHALF>
__device__ __forceinline__ void chunk4(const ulonglong2* __restrict__ Wb,
                                       const float* __restrict__ x,
                                       ull acc[4])
{
#pragma unroll
    for (int t = 0; t < KHALF; t++) {
        ull xa = pk2(x[2 * t]), xb = pk2(x[2 * t + 1]);
#pragma unroll
        for (int p = 0; p < 4; p++) {
            ulonglong2 w = Wb[p * KHALF + t];
            acc[p] = f2fma(w.x, xa, acc[p]);
            acc[p] = f2fma(w.y, xb, acc[p]);
        }
    }
}

template<int KHALF, int NPAIRS, bool RELU>
__device__ __forceinline__ void mlp_layer(const ulonglong2* __restrict__ W,
                                          const ull* __restrict__ Bp,
                                          const float* __restrict__ x,
                                          float* __restrict__ y)
{
#pragma unroll
    for (int c = 0; c < NPAIRS / 8; c++) {
        ull acc[8];
#pragma unroll
        for (int p = 0; p < 8; p++) acc[p] = Bp[c * 8 + p];
        chunk8<KHALF>(W + (c * 8) * KHALF, x, acc);
#pragma unroll
        for (int p = 0; p < 8; p++) {
            float2 r = up2(acc[p]);
            if (RELU) { r.x = fmaxf(r.x, 0.f); r.y = fmaxf(r.y, 0.f); }
            y[c * 16 + 2 * p] = r.x;
            y[c * 16 + 2 * p + 1] = r.y;
        }
    }
}

__global__ void __launch_bounds__(BLOCK, 2) frame_gnn_kernel(
    const float* __restrict__ state,
    const float* __restrict__ up_Z1_w, const float* __restrict__ up_h1_w, const float* __restrict__ up_h1_b,
    const float* __restrict__ up_g1_w1, const float* __restrict__ up_g1_b1,
    const float* __restrict__ up_g1_w2, const float* __restrict__ up_g1_b2,
    const float* __restrict__ up_Z2_w,
    const float* __restrict__ up_m_w1, const float* __restrict__ up_m_b1,
    const float* __restrict__ up_m_w2, const float* __restrict__ up_m_b2,
    const float* __restrict__ up_m_w3, const float* __restrict__ up_m_b3,
    const float* __restrict__ dn_g1_w1, const float* __restrict__ dn_g1_b1,
    const float* __restrict__ dn_g1_w2, const float* __restrict__ dn_g1_b2,
    const float* __restrict__ dn_Z2_w,
    const float* __restrict__ fr_w1, const float* __restrict__ fr_b1,
    const float* __restrict__ fr_w2, const float* __restrict__ fr_b2,
    const float* __restrict__ fr_w3, const float* __restrict__ fr_b3,
    float* __restrict__ out)
{
    extern __shared__ float sm[];
    const int tid = threadIdx.x;

    // ---------------- stage + fold + pair-pack weights ----------------
    if (tid < 64) {
        const int k = tid;
        const int base1 = OFF_L1 + (k >> 1) * 88 + (k & 1);
        const int basef = OFF_F1 + (k >> 1) * 88 + (k & 1);
        int p = 0;
        for (int a = 0; a < 8; a++) {
            for (int b = a; b < 8; b++) {
                float w = up_m_w1[k * 88 + a * 8 + b];
                float f = fr_w1[k * 80 + a * 8 + b];
                if (a != b) {
                    w += up_m_w1[k * 88 + b * 8 + a];
                    f += fr_w1[k * 80 + b * 8 + a];
                }
                sm[base1 + p * 2] = w;
                sm[basef + p * 2] = f;
                p++;
            }
        }
        for (int j = 0; j < 8; j++) {
            sm[base1 + (36 + j) * 2] = up_m_w1[k * 88 + 64 + j];
            sm[basef + (36 + j) * 2] = fr_w1[k * 80 + 64 + j];
        }
    }
    for (int e = tid; e < 64 * 64; e += BLOCK) {
        const int k = e >> 6, j = e & 63;
        const int d = ((k >> 1) * 64 + j) * 2 + (k & 1);
        sm[OFF_L2 + d] = up_m_w2[e];
        sm[OFF_F2 + d] = fr_w2[e];
    }
    for (int e = tid; e < 72 * 64; e += BLOCK) {
        const int k = e >> 6, j = e & 63;
        sm[OFF_L3 + ((k >> 1) * 64 + j) * 2 + (k & 1)] = up_m_w3[e];
    }
    for (int e = tid; e < 8 * 64; e += BLOCK) {
        const int k = e >> 6, j = e & 63;
        sm[OFF_F3 + ((k >> 1) * 64 + j) * 2 + (k & 1)] = fr_w3[e];
    }
    for (int i = tid; i < 64; i += BLOCK) {
        sm[OFF_B1P + i] = up_m_b1[i]; sm[OFF_B2P + i] = up_m_b2[i];
        sm[OFF_FB1P + i] = fr_b1[i];  sm[OFF_FB2P + i] = fr_b2[i];
    }
    for (int i = tid; i < 72; i += BLOCK) sm[OFF_B3P + i] = up_m_b3[i];
    for (int i = tid; i < 104; i += BLOCK) sm[OFF_UH1W + i] = up_h1_w[i];
    for (int i = tid; i < 32; i += BLOCK) sm[OFF_UZ1 + i] = up_Z1_w[i];
    for (int i = tid; i < 64; i += BLOCK) {
        const int k = i >> 3, j = i & 7;
        sm[OFF_G1W + i]  = up_g1_w1[k * 24 + j];
        sm[OFF_DG1W + i] = dn_g1_w1[k * 16 + j];
        sm[OFF_UZ2S + i] = up_Z2_w[k * 25 + j];
        sm[OFF_DZ2S + i] = dn_Z2_w[k * 17 + j];
    }
    if (tid < 8) {
        sm[OFF_FB3P + tid] = fr_b3[tid];
        sm[OFF_UH1B + tid] = up_h1_b[tid];
        sm[OFF_G1B + tid]  = up_g1_b1[tid];
        sm[OFF_G2W + tid]  = up_g1_w2[tid];
        sm[OFF_UZ2Z + tid] = up_Z2_w[tid * 25 + 24];
        sm[OFF_DG1B + tid] = dn_g1_b1[tid];
        sm[OFF_DG2W + tid] = dn_g1_w2[tid];
        sm[OFF_DZ2Z + tid] = dn_Z2_w[tid * 17 + 16];
    }
    if (tid == 0) { sm[OFF_G2B] = up_g1_b2[0]; sm[OFF_DG2B] = dn_g1_b2[0]; }
    __syncthreads();

    const int row = blockIdx.x * BLOCK + tid;
    if (row >= NROWS) return;

    const ulonglong2* W1 = reinterpret_cast<const ulonglong2*>(sm + OFF_L1);
    const ulonglong2* W2 = reinterpret_cast<const ulonglong2*>(sm + OFF_L2);
    const ulonglong2* W3 = reinterpret_cast<const ulonglong2*>(sm + OFF_L3);
    const ulonglong2* G1 = reinterpret_cast<const ulonglong2*>(sm + OFF_F1);
    const ulonglong2* G2 = reinterpret_cast<const ulonglong2*>(sm + OFF_F2);
    const ulonglong2* G3 = reinterpret_cast<const ulonglong2*>(sm + OFF_F3);
    const ull* B1P = reinterpret_cast<const ull*>(sm + OFF_B1P);
    const ull* B2P = reinterpret_cast<const ull*>(sm + OFF_B2P);
    const ull* B3P = reinterpret_cast<const ull*>(sm + OFF_B3P);
    const ull* FB1P = reinterpret_cast<const ull*>(sm + OFF_FB1P);
    const ull* FB2P = reinterpret_cast<const ull*>(sm + OFF_FB2P);
    const ull* FB3P = reinterpret_cast<const ull*>(sm + OFF_FB3P);
    float* scr = sm + OFF_ZM + tid;   // per-thread scratch, row stride BLOCK

    const float* s = state + (size_t)row * 25;
    float* o = out + (size_t)row * 25;

    float h0[13];
#pragma unroll
    for (int i = 0; i < 4; i++) { float v = s[i]; h0[i] = v; o[i] = v; }
#pragma unroll
    for (int i = 0; i < 9; i++) { float v = s[16 + i]; h0[4 + i] = v; o[16 + i] = v; }

    // hm8 = relu(up_h1 @ h0 + b)
    float hm8[8];
#pragma unroll
    for (int k = 0; k < 8; k++) {
        float a = sm[OFF_UH1B + k];
#pragma unroll
        for (int i = 0; i < 13; i++) a += h0[i] * sm[OFF_UH1W + k * 13 + i];
        hm8[k] = fmaxf(a, 0.f);
    }
    // gs (scalar gate)
    float gs = sm[OFF_G2B];
#pragma unroll
    for (int k = 0; k < 8; k++) {
        float a = sm[OFF_G1B + k];
#pragma unroll
        for (int i = 0; i < 8; i++) a += hm8[i] * sm[OFF_G1W + k * 8 + i];
        gs += fmaxf(a, 0.f) * sm[OFF_G2W + k];
    }
    // Zm = [Z0 @ up_Z1^T, 0, (0,0,gs)] @ up_Z2^T
    float Zm0[8], Zm1[8], Zm2a[8];
    {
        float Z0x[4], Z0y[4], Z0z[4];
#pragma unroll
        for (int j = 0; j < 4; j++) { Z0x[j] = s[4 + 3 * j]; Z0y[j] = s[5 + 3 * j]; Z0z[j] = s[6 + 3 * j]; }
        float Zu0[8], Zu1[8], Zu2[8];
#pragma unroll
        for (int k = 0; k < 8; k++) {
            float a0 = 0.f, a1 = 0.f, a2 = 0.f;
#pragma unroll
            for (int j = 0; j < 4; j++) {
                float w = sm[OFF_UZ1 + k * 4 + j];
                a0 += Z0x[j] * w; a1 += Z0y[j] * w; a2 += Z0z[j] * w;
            }
            Zu0[k] = a0; Zu1[k] = a1; Zu2[k] = a2;
        }
#pragma unroll
        for (int k = 0; k < 8; k++) {
            float a0 = 0.f, a1 = 0.f, a2 = 0.f;
#pragma unroll
            for (int m = 0; m < 8; m++) {
                float w = sm[OFF_UZ2S + k * 8 + m];
                a0 += Zu0[m] * w; a1 += Zu1[m] * w; a2 += Zu2[m] * w;
            }
            a2 += gs * sm[OFF_UZ2Z + k];
            Zm0[k] = a0; Zm1[k] = a1; Zm2a[k] = a2;
        }
    }
    // Gram (36 unique) + Frobenius norm; xv[36..43]=hm8
    float xv[44];
    float nrm = 0.f;
    {
        int p = 0;
#pragma unroll
        for (int a = 0; a < 8; a++)
#pragma unroll
            for (int b = a; b < 8; b++) {
                float v = Zm0[a] * Zm0[b] + Zm1[a] * Zm1[b] + Zm2a[a] * Zm2a[b];
                xv[p] = v;
                nrm += (a == b) ? v * v : 2.f * v * v;
                p++;
            }
    }
#pragma unroll
    for (int j = 0; j < 8; j++) xv[36 + j] = hm8[j];
    const float invFn = 1.f / (sqrtf(nrm) + 1.f);

    // spill Zm to scratch (reused in L3 consumption)
#pragma unroll
    for (int j = 0; j < 8; j++) {
        scr[j * BLOCK] = Zm0[j];
        scr[(8 + j) * BLOCK] = Zm1[j];
        scr[(16 + j) * BLOCK] = Zm2a[j];
    }

    // ---- up_m layer1 (K=44) + layer2 (K=64), relu ----
    float t1[64];
    mlp_layer<22, 32, true>(W1, B1P, xv, t1);
    float t2[64];
    mlp_layer<32, 32, true>(W2, B2P, t1, t2);

    // ---- up_m layer3: 72 out (9 chunks of 4 pairs = 8 outputs), fused consumption ----
    float uZ0[8], uZ1[8], uZ2[8], hm2[8];
#pragma unroll
    for (int k = 0; k < 8; k++) { uZ0[k] = 0.f; uZ1[k] = 0.f; uZ2[k] = 0.f; }
#pragma unroll
    for (int c = 0; c < 9; c++) {
        ull acc[4];
#pragma unroll
        for (int p = 0; p < 4; p++) acc[p] = B3P[c * 4 + p];
        chunk4<32>(W3 + (c * 4) * 32, t2, acc);
        if (c < 8) {
            // chunk c covers outputs 8c..8c+7 -> row j=c of M, all k
            const float zj0 = scr[c * BLOCK];
            const float zj1 = scr[(8 + c) * BLOCK];
            const float zj2 = scr[(16 + c) * BLOCK];
#pragma unroll
            for (int p = 0; p < 4; p++) {
                float2 mm = up2(acc[p]);
                const float m0 = mm.x * invFn, m1 = mm.y * invFn;
                const int k0 = 2 * p, k1 = 2 * p + 1;
                uZ0[k0] += zj0 * m0; uZ1[k0] += zj1 * m0; uZ2[k0] += zj2 * m0;
                uZ0[k1] += zj0 * m1; uZ1[k1] += zj1 * m1; uZ2[k1] += zj2 * m1;
            }
        } else {
#pragma unroll
            for (int p = 0; p < 4; p++) {
                float2 mm = up2(acc[p]);
                hm2[2 * p] = fmaxf(mm.x * invFn, 0.f);
                hm2[2 * p + 1] = fmaxf(mm.y * invFn, 0.f);
            }
        }
    }
    // gs2
    float gs2 = sm[OFF_DG2B];
#pragma unroll
    for (int k = 0; k < 8; k++) {
        float a = sm[OFF_DG1B + k];
#pragma unroll
        for (int i = 0; i < 8; i++) a += hm2[i] * sm[OFF_DG1W + k * 8 + i];
        gs2 += fmaxf(a, 0.f) * sm[OFF_DG2W + k];
    }
    // Y = [uZ, 0, (0,0,gs2)] @ dn_Z2^T
    float Y0[8], Y1[8], Y2[8];
#pragma unroll
    for (int k = 0; k < 8; k++) {
        float a0 = 0.f, a1 = 0.f, a2 = 0.f;
#pragma unroll
        for (int j = 0; j < 8; j++) {
            float w = sm[OFF_DZ2S + k * 8 + j];
            a0 += uZ0[j] * w; a1 += uZ1[j] * w; a2 += uZ2[j] * w;
        }
        a2 += gs2 * sm[OFF_DZ2Z + k];
        Y0[k] = a0; Y1[k] = a1; Y2[k] = a2;
    }
    // M2f pairs + norm; xv[36..43]=hm2
    float nrm2 = 0.f;
    {
        int p = 0;
#pragma unroll
        for (int a = 0; a < 8; a++)
#pragma unroll
            for (int b = a; b < 8; b++) {
                float v = Y0[a] * Y0[b] + Y1[a] * Y1[b] + Y2[a] * Y2[b];
                xv[p] = v;
                nrm2 += (a == b) ? v * v : 2.f * v * v;
                p++;
            }
    }
#pragma unroll
    for (int j = 0; j < 8; j++) xv[36 + j] = hm2[j];
    const float invFn2 = 1.f / (sqrtf(nrm2) + 1.f);

    // spill Y0,Y1 into scratch rows 0..15 (Zm is dead)
#pragma unroll
    for (int k = 0; k < 8; k++) {
        scr[k * BLOCK] = Y0[k];
        scr[(8 + k) * BLOCK] = Y1[k];
    }

    // ---- fr MLP ----
    float f1[64];
    mlp_layer<22, 32, true>(G1, FB1P, xv, f1);
    float f2[64];
    mlp_layer<32, 32, true>(G2, FB2P, f1, f2);
    float frv[8];
    {
        ull acc[4];
#pragma unroll
        for (int p = 0; p < 4; p++) acc[p] = FB3P[p];
        chunk4<32>(G3, f2, acc);
#pragma unroll
        for (int p = 0; p < 4; p++) {
            float2 r = up2(acc[p]);
            frv[2 * p] = r.x * invFn2;
            frv[2 * p + 1] = r.y * invFn2;
        }
    }
    // frame x,y from stashed Y0,Y1
    float fx = 0.f, fy = 0.f;
#pragma unroll
    for (int k = 0; k < 8; k++) {
        fx += scr[k * BLOCK] * frv[k];
        fy += scr[(8 + k) * BLOCK] * frv[k];
    }
    const float n = sqrtf(fx * fx + fy * fy) + 1e-6f;
    const float u1x = fx / n, u1y = fy / n;

    // reload Z0 from global (L2-resident), rotate, write out[4:16]
#pragma unroll
    for (int j = 0; j < 4; j++) {
        const float zx = __ldg(&s[4 + 3 * j]);
        const float zy = __ldg(&s[5 + 3 * j]);
        const float zz = __ldg(&s[6 + 3 * j]);
        o[4 + 3 * j]     = u1x * zx + u1y * zy;
        o[4 + 3 * j + 1] = -u1y * zx + u1x * zy;
        o[4 + 3 * j + 2] = zz;
    }
}

extern "C" void kernel_launch(void* const* d_in, const int* in_sizes, int n_in,
                              void* d_out, int out_size) {
    (void)in_sizes; (void)n_in; (void)out_size;
    const size_t smem_bytes = SMEM_FLOATS * sizeof(float);
    cudaFuncSetAttribute(frame_gnn_kernel, cudaFuncAttributeMaxDynamicSharedMemorySize,
                         (int)smem_bytes);
    frame_gnn_kernel<<<GRID, BLOCK, smem_bytes>>>(
        (const float*)d_in[0],
        (const float*)d_in[1], (const float*)d_in[2], (const float*)d_in[3],
        (const float*)d_in[4], (const float*)d_in[5], (const float*)d_in[6], (const float*)d_in[7],
        (const float*)d_in[8],
        (const float*)d_in[9], (const float*)d_in[10], (const float*)d_in[11], (const float*)d_in[12],
        (const float*)d_in[13], (const float*)d_in[14],
        (const float*)d_in[15], (const float*)d_in[16], (const float*)d_in[17], (const float*)d_in[18],
        (const float*)d_in[19],
        (const float*)d_in[20], (const float*)d_in[21], (const float*)d_in[22], (const float*)d_in[23],
        (const float*)d_in[24], (const float*)d_in[25],
        (float*)d_out);
}

// round 8
// speedup vs baseline: 1.3666x; 1.0977x over previous
#include <cuda_runtime.h>
#include <cuda_bf16.h>
#include <mma.h>
#include <cstdint>

using namespace nvcuda;

#define BLOCK 256
#define NROWS 262144
#define GRID (NROWS / BLOCK)   // 1024

// ---------------- scal float offsets ----------------
constexpr int F_UH1W=0, F_UH1B=104, F_G1W=112, F_G1B=176, F_G2W=184, F_G2B=192,
    F_UZ1=196, F_UZ2S=228, F_UZ2Z=292, F_DG1W=300, F_DG1B=364, F_DG2W=372,
    F_DG2B=380, F_DZ2S=384, F_DZ2Z=448, F_B1=456, F_B2=520, F_B3=584,
    F_FB1=656, F_FB2=720, F_FB3=784;   // 792 floats total

// ---------------- smem layout (bytes) ----------------
constexpr int SM_SCAL  = 0;                       // 3168B used
constexpr int SM_AHI   = 3200;                    // A_HI: 256 rows x 88 bf16 (176B/row)
constexpr int A_STRIDE = 88;                      // bf16 elems
constexpr int SM_WARP  = SM_AHI + 256 * A_STRIDE * 2;   // 48256; 8 blocks of 9728B
constexpr int D_STRIDE = 76;                      // f32 elems (304B/row)
constexpr int WARP_BLK = 32 * D_STRIDE * 4;       // 9728 (A_LO overlays D, stride 176B)
constexpr int SM_W     = SM_WARP + 8 * WARP_BLK;  // 126080
constexpr int W_L1H = SM_W,               W_L1L = W_L1H + 64*48*2;
constexpr int W_L2H = W_L1L + 64*48*2,    W_L2L = W_L2H + 64*64*2;
constexpr int W_L3H = W_L2L + 64*64*2,    W_L3L = W_L3H + 72*64*2;   // n-tile 4 spills into next (unused outputs)
constexpr int W_F1H = W_L3L + 72*64*2,    W_F1L = W_F1H + 64*48*2;
constexpr int W_F2H = W_F1L + 64*48*2,    W_F2L = W_F2H + 64*64*2;
constexpr int W_F3H = W_F2L + 64*64*2,    W_F3L = W_F3H + 8*64*2;    // reads spill into F3L / pad
constexpr int SMEM_BYTES = W_F3L + 8*64*2 + 1024;  // 204928

// gram pair index -> (a,b)
__device__ const unsigned char PA[36] = {0,0,0,0,0,0,0,0, 1,1,1,1,1,1,1, 2,2,2,2,2,2,
                                         3,3,3,3,3, 4,4,4,4, 5,5,5, 6,6, 7};
__device__ const unsigned char PB[36] = {0,1,2,3,4,5,6,7, 1,2,3,4,5,6,7, 2,3,4,5,6,7,
                                         3,4,5,6,7, 4,5,6,7, 5,6,7, 6,7, 7};

__device__ __forceinline__ void wput(char* smc, int offH, int offL, int idx, float v) {
    __nv_bfloat16 h = __float2bfloat16(v);
    __nv_bfloat16 l = __float2bfloat16(v - __bfloat162float(h));
    reinterpret_cast<__nv_bfloat16*>(smc + offH)[idx] = h;
    reinterpret_cast<__nv_bfloat16*>(smc + offL)[idx] = l;
}

// write 48 act columns (split) for warp-row rr (cols 44..47 zero)
__device__ __forceinline__ void write_acts48(char* smc, int w, int rr, const float* xv) {
    __nv_bfloat16* AH = reinterpret_cast<__nv_bfloat16*>(smc + SM_AHI) + (size_t)(w * 32 + rr) * A_STRIDE;
    __nv_bfloat16* AL = reinterpret_cast<__nv_bfloat16*>(smc + SM_WARP + w * WARP_BLK) + (size_t)rr * A_STRIDE;
#pragma unroll
    for (int c = 0; c < 48; c++) {
        float v = (c < 44) ? xv[c] : 0.f;
        __nv_bfloat16 h = __float2bfloat16(v);
        __nv_bfloat16 l = __float2bfloat16(v - __bfloat162float(h));
        AH[c] = h; AL[c] = l;
    }
}

// Generic layer: D[32,16*NT] = A[32,16*KT] @ W^T, 3-term bf16 split.
// If NT==5 the last n-tile is stored to the f32 scratch at the warp's A_HI block
// (avoids D stride overflow); consumed only by the L3 post.
template<int KT, int NT, int KPAD>
__device__ __forceinline__ void mm_layer(char* smc, int w, int wHiOff, int wLoOff) {
    wmma::fragment<wmma::accumulator, 16, 16, 16, float> c[2][NT];
#pragma unroll
    for (int mt = 0; mt < 2; mt++)
#pragma unroll
        for (int nt = 0; nt < NT; nt++) wmma::fill_fragment(c[mt][nt], 0.0f);
    const __nv_bfloat16* AH = reinterpret_cast<const __nv_bfloat16*>(smc + SM_AHI) + (size_t)(w * 32) * A_STRIDE;
    const __nv_bfloat16* AL = reinterpret_cast<const __nv_bfloat16*>(smc + SM_WARP + w * WARP_BLK);
    const __nv_bfloat16* WH = reinterpret_cast<const __nv_bfloat16*>(smc + wHiOff);
    const __nv_bfloat16* WL = reinterpret_cast<const __nv_bfloat16*>(smc + wLoOff);
#pragma unroll
    for (int kt = 0; kt < KT; kt++) {
        wmma::fragment<wmma::matrix_a, 16, 16, 16, __nv_bfloat16, wmma::row_major> ah[2], al[2];
#pragma unroll
        for (int mt = 0; mt < 2; mt++) {
            wmma::load_matrix_sync(ah[mt], AH + mt * 16 * A_STRIDE + kt * 16, A_STRIDE);
            wmma::load_matrix_sync(al[mt], AL + mt * 16 * A_STRIDE + kt * 16, A_STRIDE);
        }
#pragma unroll
        for (int nt = 0; nt < NT; nt++) {
            wmma::fragment<wmma::matrix_b, 16, 16, 16, __nv_bfloat16, wmma::col_major> bh, bl;
            wmma::load_matrix_sync(bh, WH + nt * 16 * KPAD + kt * 16, KPAD);
            wmma::load_matrix_sync(bl, WL + nt * 16 * KPAD + kt * 16, KPAD);
#pragma unroll
            for (int mt = 0; mt < 2; mt++) {
                wmma::mma_sync(c[mt][nt], ah[mt], bh, c[mt][nt]);
                wmma::mma_sync(c[mt][nt], ah[mt], bl, c[mt][nt]);
                wmma::mma_sync(c[mt][nt], al[mt], bh, c[mt][nt]);
            }
        }
    }
    float* D = reinterpret_cast<float*>(smc + SM_WARP + w * WARP_BLK);
    float* T = reinterpret_cast<float*>(smc + SM_AHI + (size_t)w * 32 * (A_STRIDE * 2));
#pragma unroll
    for (int mt = 0; mt < 2; mt++)
#pragma unroll
        for (int nt = 0; nt < NT; nt++) {
            if (NT == 5 && nt == 4)
                wmma::store_matrix_sync(T + mt * 16 * 16, c[mt][nt], 16, wmma::mem_row_major);
            else
                wmma::store_matrix_sync(D + mt * 16 * D_STRIDE + nt * 16, c[mt][nt], D_STRIDE, wmma::mem_row_major);
        }
}

// elementwise post for N=64 relu layers: D -> bias/relu -> A hi/lo
__device__ __forceinline__ void post_relu(char* smc, const float* scal, int biasF, int w, int lane) {
    const float* D = reinterpret_cast<const float*>(smc + SM_WARP + w * WARP_BLK);
    const float b0 = scal[biasF + lane], b1 = scal[biasF + 32 + lane];
    float v[64];
#pragma unroll
    for (int rr = 0; rr < 32; rr++) {
        v[2 * rr]     = fmaxf(D[rr * D_STRIDE + lane] + b0, 0.f);
        v[2 * rr + 1] = fmaxf(D[rr * D_STRIDE + 32 + lane] + b1, 0.f);
    }
    __syncwarp();   // all reads of D done before A_LO (overlay) writes
    __nv_bfloat16* AH = reinterpret_cast<__nv_bfloat16*>(smc + SM_AHI) + (size_t)(w * 32) * A_STRIDE;
    __nv_bfloat16* AL = reinterpret_cast<__nv_bfloat16*>(smc + SM_WARP + w * WARP_BLK);
#pragma unroll
    for (int rr = 0; rr < 32; rr++) {
        float v0 = v[2 * rr], v1 = v[2 * rr + 1];
        __nv_bfloat16 h0 = __float2bfloat16(v0), h1 = __float2bfloat16(v1);
        __nv_bfloat16 l0 = __float2bfloat16(v0 - __bfloat162float(h0));
        __nv_bfloat16 l1 = __float2bfloat16(v1 - __bfloat162float(h1));
        AH[rr * A_STRIDE + lane] = h0; AH[rr * A_STRIDE + 32 + lane] = h1;
        AL[rr * A_STRIDE + lane] = l0; AL[rr * A_STRIDE + 32 + lane] = l1;
    }
}

__global__ void __launch_bounds__(BLOCK, 1) frame_gnn_wmma_kernel(
    const float* __restrict__ state,
    const float* __restrict__ up_Z1_w, const float* __restrict__ up_h1_w, const float* __restrict__ up_h1_b,
    const float* __restrict__ up_g1_w1, const float* __restrict__ up_g1_b1,
    const float* __restrict__ up_g1_w2, const float* __restrict__ up_g1_b2,
    const float* __restrict__ up_Z2_w,
    const float* __restrict__ up_m_w1, const float* __restrict__ up_m_b1,
    const float* __restrict__ up_m_w2, const float* __restrict__ up_m_b2,
    const float* __restrict__ up_m_w3, const float* __restrict__ up_m_b3,
    const float* __restrict__ dn_g1_w1, const float* __restrict__ dn_g1_b1,
    const float* __restrict__ dn_g1_w2, const float* __restrict__ dn_g1_b2,
    const float* __restrict__ dn_Z2_w,
    const float* __restrict__ fr_w1, const float* __restrict__ fr_b1,
    const float* __restrict__ fr_w2, const float* __restrict__ fr_b2,
    const float* __restrict__ fr_w3, const float* __restrict__ fr_b3,
    float* __restrict__ out)
{
    extern __shared__ char smc[];
    float* scal = reinterpret_cast<float*>(smc + SM_SCAL);
    const int tid = threadIdx.x;

    // ---------------- stage scalar weights ----------------
    for (int i = tid; i < 104; i += BLOCK) scal[F_UH1W + i] = up_h1_w[i];
    for (int i = tid; i < 32; i += BLOCK)  scal[F_UZ1 + i] = up_Z1_w[i];
    for (int i = tid; i < 64; i += BLOCK) {
        const int k = i >> 3, j = i & 7;
        scal[F_G1W + i]  = up_g1_w1[k * 24 + j];
        scal[F_DG1W + i] = dn_g1_w1[k * 16 + j];
        scal[F_UZ2S + i] = up_Z2_w[k * 25 + j];
        scal[F_DZ2S + i] = dn_Z2_w[k * 17 + j];
        scal[F_B1 + i] = up_m_b1[i];  scal[F_B2 + i] = up_m_b2[i];
        scal[F_FB1 + i] = fr_b1[i];   scal[F_FB2 + i] = fr_b2[i];
    }
    for (int i = tid; i < 72; i += BLOCK) scal[F_B3 + i] = up_m_b3[i];
    if (tid < 8) {
        scal[F_UH1B + tid] = up_h1_b[tid];
        scal[F_G1B + tid]  = up_g1_b1[tid];
        scal[F_G2W + tid]  = up_g1_w2[tid];
        scal[F_UZ2Z + tid] = up_Z2_w[tid * 25 + 24];
        scal[F_DG1B + tid] = dn_g1_b1[tid];
        scal[F_DG2W + tid] = dn_g1_w2[tid];
        scal[F_DZ2Z + tid] = dn_Z2_w[tid * 17 + 16];
        scal[F_FB3 + tid]  = fr_b3[tid];
    }
    if (tid == 0) { scal[F_G2B] = up_g1_b2[0]; scal[F_DG2B] = dn_g1_b2[0]; }

    // ---------------- stage weight tiles (bf16 split) ----------------
    for (int e = tid; e < 64 * 48; e += BLOCK) {   // L1 / F1 (folded gram, K=48)
        const int n = e / 48, k = e % 48;
        float v1 = 0.f, vf = 0.f;
        if (k < 36) {
            const int a = PA[k], b = PB[k];
            v1 = up_m_w1[n * 88 + a * 8 + b];
            vf = fr_w1[n * 80 + a * 8 + b];
            if (a != b) { v1 += up_m_w1[n * 88 + b * 8 + a]; vf += fr_w1[n * 80 + b * 8 + a]; }
        } else if (k < 44) {
            v1 = up_m_w1[n * 88 + 64 + (k - 36)];
            vf = fr_w1[n * 80 + 64 + (k - 36)];
        }
        wput(smc, W_L1H, W_L1L, n * 48 + k, v1);
        wput(smc, W_F1H, W_F1L, n * 48 + k, vf);
    }
    for (int e = tid; e < 64 * 64; e += BLOCK) {   // L2 / F2
        const int n = e >> 6, k = e & 63;
        wput(smc, W_L2H, W_L2L, e, up_m_w2[n * 64 + k]);
        wput(smc, W_F2H, W_F2L, e, fr_w2[n * 64 + k]);
    }
    for (int e = tid; e < 72 * 64; e += BLOCK)     // L3
        wput(smc, W_L3H, W_L3L, e, up_m_w3[e]);
    for (int e = tid; e < 8 * 64; e += BLOCK)      // F3
        wput(smc, W_F3H, W_F3L, e, fr_w3[e]);
    __syncthreads();

    const int w = tid >> 5, lane = tid & 31;
    const int row = blockIdx.x * BLOCK + tid;
    const float* s = state + (size_t)row * 25;
    float* o = out + (size_t)row * 25;

    // ---------------- front (SIMT) ----------------
    float h0[13];
#pragma unroll
    for (int i = 0; i < 4; i++) { float v = s[i]; h0[i] = v; o[i] = v; }
#pragma unroll
    for (int i = 0; i < 9; i++) { float v = s[16 + i]; h0[4 + i] = v; o[16 + i] = v; }
    float hm8[8];
#pragma unroll
    for (int k = 0; k < 8; k++) {
        float a = scal[F_UH1B + k];
#pragma unroll
        for (int i = 0; i < 13; i++) a += h0[i] * scal[F_UH1W + k * 13 + i];
        hm8[k] = fmaxf(a, 0.f);
    }
    float gs = scal[F_G2B];
#pragma unroll
    for (int k = 0; k < 8; k++) {
        float a = scal[F_G1B + k];
#pragma unroll
        for (int i = 0; i < 8; i++) a += hm8[i] * scal[F_G1W + k * 8 + i];
        gs += fmaxf(a, 0.f) * scal[F_G2W + k];
    }
    float Zm0[8], Zm1[8], Zm2[8];
    {
        float Z0x[4], Z0y[4], Z0z[4];
#pragma unroll
        for (int j = 0; j < 4; j++) { Z0x[j] = s[4 + 3 * j]; Z0y[j] = s[5 + 3 * j]; Z0z[j] = s[6 + 3 * j]; }
        float Zu0[8], Zu1[8], Zu2[8];
#pragma unroll
        for (int k = 0; k < 8; k++) {
            float a0 = 0.f, a1 = 0.f, a2 = 0.f;
#pragma unroll
            for (int j = 0; j < 4; j++) {
                float wv = scal[F_UZ1 + k * 4 + j];
                a0 += Z0x[j] * wv; a1 += Z0y[j] * wv; a2 += Z0z[j] * wv;
            }
            Zu0[k] = a0; Zu1[k] = a1; Zu2[k] = a2;
        }
#pragma unroll
        for (int k = 0; k < 8; k++) {
            float a0 = 0.f, a1 = 0.f, a2 = 0.f;
#pragma unroll
            for (int m = 0; m < 8; m++) {
                float wv = scal[F_UZ2S + k * 8 + m];
                a0 += Zu0[m] * wv; a1 += Zu1[m] * wv; a2 += Zu2[m] * wv;
            }
            a2 += gs * scal[F_UZ2Z + k];
            Zm0[k] = a0; Zm1[k] = a1; Zm2[k] = a2;
        }
    }
    float xv[44], nrm = 0.f;
    {
        int p = 0;
#pragma unroll
        for (int a = 0; a < 8; a++)
#pragma unroll
            for (int b = a; b < 8; b++) {
                float v = Zm0[a] * Zm0[b] + Zm1[a] * Zm1[b] + Zm2[a] * Zm2[b];
                xv[p] = v;
                nrm += (a == b) ? v * v : 2.f * v * v;
                p++;
            }
    }
#pragma unroll
    for (int j = 0; j < 8; j++) xv[36 + j] = hm8[j];
    const float invFn = 1.f / (sqrtf(nrm) + 1.f);

    write_acts48(smc, w, lane, xv);
    __syncwarp();

    // ---------------- up_m MLP ----------------
    mm_layer<3, 4, 48>(smc, w, W_L1H, W_L1L);
    __syncwarp();
    post_relu(smc, scal, F_B1, w, lane);
    __syncwarp();
    mm_layer<4, 4, 64>(smc, w, W_L2H, W_L2L);
    __syncwarp();
    post_relu(smc, scal, F_B2, w, lane);
    __syncwarp();
    mm_layer<4, 5, 64>(smc, w, W_L3H, W_L3L);
    __syncwarp();

    // ---------------- L3 post (row-coupled, SIMT) ----------------
    float Yx[8], Yy[8], invFn2;
    {
        float rg[72];
        const float* D = reinterpret_cast<const float*>(smc + SM_WARP + w * WARP_BLK);
        const float* T = reinterpret_cast<const float*>(smc + SM_AHI + (size_t)w * 32 * (A_STRIDE * 2));
#pragma unroll
        for (int i = 0; i < 64; i++) rg[i] = D[lane * D_STRIDE + i];
#pragma unroll
        for (int j = 0; j < 8; j++) rg[64 + j] = T[lane * 16 + j];
        __syncwarp();
        float uZ0[8], uZ1[8], uZ2[8], hm2[8];
#pragma unroll
        for (int k = 0; k < 8; k++) { uZ0[k] = 0.f; uZ1[k] = 0.f; uZ2[k] = 0.f; }
#pragma unroll
        for (int j = 0; j < 8; j++) {
#pragma unroll
            for (int k = 0; k < 8; k++) {
                const int idx = j * 8 + k;
                float m = (rg[idx] + scal[F_B3 + idx]) * invFn;
                uZ0[k] += Zm0[j] * m; uZ1[k] += Zm1[j] * m; uZ2[k] += Zm2[j] * m;
            }
        }
#pragma unroll
        for (int j = 0; j < 8; j++)
            hm2[j] = fmaxf((rg[64 + j] + scal[F_B3 + 64 + j]) * invFn, 0.f);
        float gs2 = scal[F_DG2B];
#pragma unroll
        for (int k = 0; k < 8; k++) {
            float a = scal[F_DG1B + k];
#pragma unroll
            for (int i = 0; i < 8; i++) a += hm2[i] * scal[F_DG1W + k * 8 + i];
            gs2 += fmaxf(a, 0.f) * scal[F_DG2W + k];
        }
        float Yz[8];
#pragma unroll
        for (int k = 0; k < 8; k++) {
            float a0 = 0.f, a1 = 0.f, a2 = 0.f;
#pragma unroll
            for (int j = 0; j < 8; j++) {
                float wv = scal[F_DZ2S + k * 8 + j];
                a0 += uZ0[j] * wv; a1 += uZ1[j] * wv; a2 += uZ2[j] * wv;
            }
            a2 += gs2 * scal[F_DZ2Z + k];
            Yx[k] = a0; Yy[k] = a1; Yz[k] = a2;
        }
        float nrm2 = 0.f;
        {
            int p = 0;
#pragma unroll
            for (int a = 0; a < 8; a++)
#pragma unroll
                for (int b = a; b < 8; b++) {
                    float v = Yx[a] * Yx[b] + Yy[a] * Yy[b] + Yz[a] * Yz[b];
                    xv[p] = v;
                    nrm2 += (a == b) ? v * v : 2.f * v * v;
                    p++;
                }
        }
#pragma unroll
        for (int j = 0; j < 8; j++) xv[36 + j] = hm2[j];
        invFn2 = 1.f / (sqrtf(nrm2) + 1.f);
    }
    write_acts48(smc, w, lane, xv);
    __syncwarp();

    // ---------------- fr MLP ----------------
    mm_layer<3, 4, 48>(smc, w, W_F1H, W_F1L);
    __syncwarp();
    post_relu(smc, scal, F_FB1, w, lane);
    __syncwarp();
    mm_layer<4, 4, 64>(smc, w, W_F2H, W_F2L);
    __syncwarp();
    post_relu(smc, scal, F_FB2, w, lane);
    __syncwarp();
    mm_layer<4, 1, 64>(smc, w, W_F3H, W_F3L);
    __syncwarp();

    // ---------------- F3 post + frame + writeback ----------------
    float frv[8];
    {
        const float* D = reinterpret_cast<const float*>(smc + SM_WARP + w * WARP_BLK);
#pragma unroll
        for (int k = 0; k < 8; k++)
            frv[k] = (D[lane * D_STRIDE + k] + scal[F_FB3 + k]) * invFn2;
    }
    float fx = 0.f, fy = 0.f;
#pragma unroll
    for (int k = 0; k < 8; k++) { fx += Yx[k] * frv[k]; fy += Yy[k] * frv[k]; }
    const float nn = sqrtf(fx * fx + fy * fy) + 1e-6f;
    const float u1x = fx / nn, u1y = fy / nn;
#pragma unroll
    for (int j = 0; j < 4; j++) {
        const float zx = __ldg(&s[4 + 3 * j]);
        const float zy = __ldg(&s[5 + 3 * j]);
        const float zz = __ldg(&s[6 + 3 * j]);
        o[4 + 3 * j]     = u1x * zx + u1y * zy;
        o[4 + 3 * j + 1] = -u1y * zx + u1x * zy;
        o[4 + 3 * j + 2] = zz;
    }
}

extern "C" void kernel_launch(void* const* d_in, const int* in_sizes, int n_in,
                              void* d_out, int out_size) {
    (void)in_sizes; (void)n_in; (void)out_size;
    cudaFuncSetAttribute(frame_gnn_wmma_kernel, cudaFuncAttributeMaxDynamicSharedMemorySize,
                         SMEM_BYTES);
    frame_gnn_wmma_kernel<<<GRID, BLOCK, SMEM_BYTES>>>(
        (const float*)d_in[0],
        (const float*)d_in[1], (const float*)d_in[2], (const float*)d_in[3],
        (const float*)d_in[4], (const float*)d_in[5], (const float*)d_in[6], (const float*)d_in[7],
        (const float*)d_in[8],
        (const float*)d_in[9], (const float*)d_in[10], (const float*)d_in[11], (const float*)d_in[12],
        (const float*)d_in[13], (const float*)d_in[14],
        (const float*)d_in[15], (const float*)d_in[16], (const float*)d_in[17], (const float*)d_in[18],
        (const float*)d_in[19],
        (const float*)d_in[20], (const float*)d_in[21], (const float*)d_in[22], (const float*)d_in[23],
        (const float*)d_in[24], (const float*)d_in[25],
        (float*)d_out);
}

// round 9
// speedup vs baseline: 2.2543x; 1.6496x over previous
#include <cuda_runtime.h>
#include <cuda_bf16.h>
#include <cstdint>

#define BLOCK 256
#define NROWS 262144
#define GRID (NROWS / BLOCK)   // 1024

constexpr int KPAD = 72;   // weight k stride (bf16 elems) -> conflict-free B loads
constexpr int APAD = 56;   // acts col stride (bf16 elems) -> conflict-free A loads
constexpr int DPAD = 74;   // D scratch stride (f32 elems)

// ---------------- scal float offsets ----------------
constexpr int F_UH1W=0, F_UH1B=104, F_G1W=112, F_G1B=176, F_G2W=184, F_G2B=192,
    F_UZ1=196, F_UZ2S=228, F_UZ2Z=292, F_DG1W=300, F_DG1B=364, F_DG2W=372,
    F_DG2B=380, F_DZ2S=384, F_DZ2Z=448, F_B1=456, F_B2=520, F_B3=584,
    F_FB1=656, F_FB2=720, F_FB3=784;   // 792 floats

// ---------------- smem layout ----------------
constexpr int SM_WT = 3584;                      // weights base (bytes)
// weight offsets in bf16 elems from SM_WT
constexpr int WH_L1=0,     WL_L1=4608,  WH_L2=9216,  WL_L2=13824,
              WH_L3=18432, WL_L3=23616, WH_F1=28800, WL_F1=33408,
              WH_F2=38016, WL_F2=42624, WH_F3=47232, WL_F3=47808;  // end 48384 elems
constexpr int SM_WARP  = SM_WT + 48384 * 2;      // 100352
constexpr int WARP_BLK = 9472;                   // per-warp scratch: acts(7168) / D(32*74*4=9472)
constexpr int SMEM_BYTES = SM_WARP + 8 * WARP_BLK;   // 176128

// gram pair index -> (a,b)
__device__ const unsigned char PA[36] = {0,0,0,0,0,0,0,0, 1,1,1,1,1,1,1, 2,2,2,2,2,2,
                                         3,3,3,3,3, 4,4,4,4, 5,5,5, 6,6, 7};
__device__ const unsigned char PB[36] = {0,1,2,3,4,5,6,7, 1,2,3,4,5,6,7, 2,3,4,5,6,7,
                                         3,4,5,6,7, 4,5,6,7, 5,6,7, 6,7, 7};

// ---------------- helpers ----------------
__device__ __forceinline__ void cvt2(float v0, float v1, uint32_t& hp, uint32_t& lp) {
    __nv_bfloat16 h0 = __float2bfloat16(v0), h1 = __float2bfloat16(v1);
    float r0 = v0 - __bfloat162float(h0), r1 = v1 - __bfloat162float(h1);
    __nv_bfloat16 l0 = __float2bfloat16(r0), l1 = __float2bfloat16(r1);
    __nv_bfloat162 hh; hh.x = h0; hh.y = h1;
    __nv_bfloat162 ll; ll.x = l0; ll.y = l1;
    hp = *reinterpret_cast<uint32_t*>(&hh);
    lp = *reinterpret_cast<uint32_t*>(&ll);
}

__device__ __forceinline__ void mma16816(float* d, const uint32_t* a, uint32_t b0, uint32_t b1) {
    asm volatile(
        "mma.sync.aligned.m16n8k16.row.col.f32.bf16.bf16.f32 "
        "{%0,%1,%2,%3}, {%4,%5,%6,%7}, {%8,%9}, {%0,%1,%2,%3};"
        : "+f"(d[0]), "+f"(d[1]), "+f"(d[2]), "+f"(d[3])
        : "r"(a[0]), "r"(a[1]), "r"(a[2]), "r"(a[3]), "r"(b0), "r"(b1));
}

// Layer with A from registers (previous D, bias+relu already applied).
template<int KT, int NT>
__device__ __forceinline__ void layer_rr(const float (&p)[2][2*KT][4], float (&dn)[2][NT][4],
                                         const uint16_t* WH, const uint16_t* WL,
                                         const float* bias, int gid, int tig) {
#pragma unroll
    for (int mt = 0; mt < 2; mt++)
#pragma unroll
        for (int nt = 0; nt < NT; nt++) {
            float2 b = *reinterpret_cast<const float2*>(bias + nt * 8 + 2 * tig);
            dn[mt][nt][0] = b.x; dn[mt][nt][1] = b.y;
            dn[mt][nt][2] = b.x; dn[mt][nt][3] = b.y;
        }
#pragma unroll
    for (int kt = 0; kt < KT; kt++) {
        uint32_t aH[2][4], aL[2][4];
#pragma unroll
        for (int mt = 0; mt < 2; mt++) {
            cvt2(p[mt][2*kt][0],   p[mt][2*kt][1],   aH[mt][0], aL[mt][0]);
            cvt2(p[mt][2*kt][2],   p[mt][2*kt][3],   aH[mt][1], aL[mt][1]);
            cvt2(p[mt][2*kt+1][0], p[mt][2*kt+1][1], aH[mt][2], aL[mt][2]);
            cvt2(p[mt][2*kt+1][2], p[mt][2*kt+1][3], aH[mt][3], aL[mt][3]);
        }
#pragma unroll
        for (int nt = 0; nt < NT; nt++) {
            const uint32_t* ph = reinterpret_cast<const uint32_t*>(WH + (nt*8+gid)*KPAD + kt*16 + 2*tig);
            const uint32_t* pl = reinterpret_cast<const uint32_t*>(WL + (nt*8+gid)*KPAD + kt*16 + 2*tig);
            uint32_t bh0 = ph[0], bh1 = ph[4], bl0 = pl[0], bl1 = pl[4];
#pragma unroll
            for (int mt = 0; mt < 2; mt++) {
                mma16816(dn[mt][nt], aH[mt], bh0, bh1);
                mma16816(dn[mt][nt], aH[mt], bl0, bl1);
                mma16816(dn[mt][nt], aL[mt], bh0, bh1);
            }
        }
    }
}

// Layer with A from smem acts (hi/lo planes, APAD stride).
template<int KT, int NT>
__device__ __forceinline__ void layer_sm(const uint16_t* actH, const uint16_t* actL,
                                         float (&dn)[2][NT][4],
                                         const uint16_t* WH, const uint16_t* WL,
                                         const float* bias, int gid, int tig) {
#pragma unroll
    for (int mt = 0; mt < 2; mt++)
#pragma unroll
        for (int nt = 0; nt < NT; nt++) {
            float2 b = *reinterpret_cast<const float2*>(bias + nt * 8 + 2 * tig);
            dn[mt][nt][0] = b.x; dn[mt][nt][1] = b.y;
            dn[mt][nt][2] = b.x; dn[mt][nt][3] = b.y;
        }
#pragma unroll
    for (int kt = 0; kt < KT; kt++) {
        uint32_t aH[2][4], aL[2][4];
#pragma unroll
        for (int mt = 0; mt < 2; mt++) {
            const int r0 = mt * 16 + gid, c0 = kt * 16 + 2 * tig;
            aH[mt][0] = *reinterpret_cast<const uint32_t*>(actH + r0 * APAD + c0);
            aH[mt][1] = *reinterpret_cast<const uint32_t*>(actH + (r0 + 8) * APAD + c0);
            aH[mt][2] = *reinterpret_cast<const uint32_t*>(actH + r0 * APAD + c0 + 8);
            aH[mt][3] = *reinterpret_cast<const uint32_t*>(actH + (r0 + 8) * APAD + c0 + 8);
            aL[mt][0] = *reinterpret_cast<const uint32_t*>(actL + r0 * APAD + c0);
            aL[mt][1] = *reinterpret_cast<const uint32_t*>(actL + (r0 + 8) * APAD + c0);
            aL[mt][2] = *reinterpret_cast<const uint32_t*>(actL + r0 * APAD + c0 + 8);
            aL[mt][3] = *reinterpret_cast<const uint32_t*>(actL + (r0 + 8) * APAD + c0 + 8);
        }
#pragma unroll
        for (int nt = 0; nt < NT; nt++) {
            const uint32_t* ph = reinterpret_cast<const uint32_t*>(WH + (nt*8+gid)*KPAD + kt*16 + 2*tig);
            const uint32_t* pl = reinterpret_cast<const uint32_t*>(WL + (nt*8+gid)*KPAD + kt*16 + 2*tig);
            uint32_t bh0 = ph[0], bh1 = ph[4], bl0 = pl[0], bl1 = pl[4];
#pragma unroll
            for (int mt = 0; mt < 2; mt++) {
                mma16816(dn[mt][nt], aH[mt], bh0, bh1);
                mma16816(dn[mt][nt], aH[mt], bl0, bl1);
                mma16816(dn[mt][nt], aL[mt], bh0, bh1);
            }
        }
    }
}

template<int NT>
__device__ __forceinline__ void relu_d(float (&d)[2][NT][4]) {
#pragma unroll
    for (int mt = 0; mt < 2; mt++)
#pragma unroll
        for (int nt = 0; nt < NT; nt++)
#pragma unroll
            for (int i = 0; i < 4; i++) d[mt][nt][i] = fmaxf(d[mt][nt][i], 0.f);
}

template<int NT>
__device__ __forceinline__ void store_D(float* dscr, const float (&d)[2][NT][4], int gid, int tig) {
#pragma unroll
    for (int mt = 0; mt < 2; mt++)
#pragma unroll
        for (int nt = 0; nt < NT; nt++) {
            *reinterpret_cast<float2*>(dscr + (mt*16+gid)*DPAD + nt*8 + 2*tig) =
                make_float2(d[mt][nt][0], d[mt][nt][1]);
            *reinterpret_cast<float2*>(dscr + (mt*16+gid+8)*DPAD + nt*8 + 2*tig) =
                make_float2(d[mt][nt][2], d[mt][nt][3]);
        }
}

__device__ __forceinline__ void write_acts(uint16_t* actH, uint16_t* actL, int lane, const float* xv) {
    uint32_t* ah = reinterpret_cast<uint32_t*>(actH + lane * APAD);
    uint32_t* al = reinterpret_cast<uint32_t*>(actL + lane * APAD);
#pragma unroll
    for (int c = 0; c < 48; c += 2) {
        float v0 = (c < 44) ? xv[c] : 0.f;
        float v1 = (c + 1 < 44) ? xv[c + 1] : 0.f;
        uint32_t hp, lp; cvt2(v0, v1, hp, lp);
        ah[c / 2] = hp; al[c / 2] = lp;
    }
}

__global__ void __launch_bounds__(BLOCK, 1) frame_gnn_mma_kernel(
    const float* __restrict__ state,
    const float* __restrict__ up_Z1_w, const float* __restrict__ up_h1_w, const float* __restrict__ up_h1_b,
    const float* __restrict__ up_g1_w1, const float* __restrict__ up_g1_b1,
    const float* __restrict__ up_g1_w2, const float* __restrict__ up_g1_b2,
    const float* __restrict__ up_Z2_w,
    const float* __restrict__ up_m_w1, const float* __restrict__ up_m_b1,
    const float* __restrict__ up_m_w2, const float* __restrict__ up_m_b2,
    const float* __restrict__ up_m_w3, const float* __restrict__ up_m_b3,
    const float* __restrict__ dn_g1_w1, const float* __restrict__ dn_g1_b1,
    const float* __restrict__ dn_g1_w2, const float* __restrict__ dn_g1_b2,
    const float* __restrict__ dn_Z2_w,
    const float* __restrict__ fr_w1, const float* __restrict__ fr_b1,
    const float* __restrict__ fr_w2, const float* __restrict__ fr_b2,
    const float* __restrict__ fr_w3, const float* __restrict__ fr_b3,
    float* __restrict__ out)
{
    extern __shared__ char smc[];
    float* scal = reinterpret_cast<float*>(smc);
    uint16_t* WT = reinterpret_cast<uint16_t*>(smc + SM_WT);
    const int tid = threadIdx.x;

    // ---------------- stage scalar weights ----------------
    for (int i = tid; i < 104; i += BLOCK) scal[F_UH1W + i] = up_h1_w[i];
    for (int i = tid; i < 32; i += BLOCK)  scal[F_UZ1 + i] = up_Z1_w[i];
    for (int i = tid; i < 64; i += BLOCK) {
        const int k = i >> 3, j = i & 7;
        scal[F_G1W + i]  = up_g1_w1[k * 24 + j];
        scal[F_DG1W + i] = dn_g1_w1[k * 16 + j];
        scal[F_UZ2S + i] = up_Z2_w[k * 25 + j];
        scal[F_DZ2S + i] = dn_Z2_w[k * 17 + j];
        scal[F_B1 + i] = up_m_b1[i];  scal[F_B2 + i] = up_m_b2[i];
        scal[F_FB1 + i] = fr_b1[i];   scal[F_FB2 + i] = fr_b2[i];
    }
    for (int i = tid; i < 72; i += BLOCK) scal[F_B3 + i] = up_m_b3[i];
    if (tid < 8) {
        scal[F_UH1B + tid] = up_h1_b[tid];
        scal[F_G1B + tid]  = up_g1_b1[tid];
        scal[F_G2W + tid]  = up_g1_w2[tid];
        scal[F_UZ2Z + tid] = up_Z2_w[tid * 25 + 24];
        scal[F_DG1B + tid] = dn_g1_b1[tid];
        scal[F_DG2W + tid] = dn_g1_w2[tid];
        scal[F_DZ2Z + tid] = dn_Z2_w[tid * 17 + 16];
        scal[F_FB3 + tid]  = fr_b3[tid];
    }
    if (tid == 0) { scal[F_G2B] = up_g1_b2[0]; scal[F_DG2B] = dn_g1_b2[0]; }

    // ---------------- stage weight matrices (bf16 split, [n][KPAD]) ----------------
    auto wsplit = [&](int offH, int offL, int idx, float v) {
        __nv_bfloat16 h = __float2bfloat16(v);
        __nv_bfloat16 l = __float2bfloat16(v - __bfloat162float(h));
        WT[offH + idx] = *reinterpret_cast<uint16_t*>(&h);
        WT[offL + idx] = *reinterpret_cast<uint16_t*>(&l);
    };
    for (int e = tid; e < 64 * KPAD; e += BLOCK) {   // L1 / F1 (folded gram)
        const int n = e / KPAD, k = e % KPAD;
        float v1 = 0.f, vf = 0.f;
        if (k < 36) {
            const int a = PA[k], b = PB[k];
            v1 = up_m_w1[n * 88 + a * 8 + b];
            vf = fr_w1[n * 80 + a * 8 + b];
            if (a != b) { v1 += up_m_w1[n * 88 + b * 8 + a]; vf += fr_w1[n * 80 + b * 8 + a]; }
        } else if (k < 44) {
            v1 = up_m_w1[n * 88 + 64 + (k - 36)];
            vf = fr_w1[n * 80 + 64 + (k - 36)];
        }
        wsplit(WH_L1, WL_L1, e, v1);
        wsplit(WH_F1, WL_F1, e, vf);
    }
    for (int e = tid; e < 64 * KPAD; e += BLOCK) {   // L2 / F2
        const int n = e / KPAD, k = e % KPAD;
        float v2 = (k < 64) ? up_m_w2[n * 64 + k] : 0.f;
        float vg = (k < 64) ? fr_w2[n * 64 + k] : 0.f;
        wsplit(WH_L2, WL_L2, e, v2);
        wsplit(WH_F2, WL_F2, e, vg);
    }
    for (int e = tid; e < 72 * KPAD; e += BLOCK) {   // L3
        const int n = e / KPAD, k = e % KPAD;
        wsplit(WH_L3, WL_L3, e, (k < 64) ? up_m_w3[n * 64 + k] : 0.f);
    }
    for (int e = tid; e < 8 * KPAD; e += BLOCK) {    // F3
        const int n = e / KPAD, k = e % KPAD;
        wsplit(WH_F3, WL_F3, e, (k < 64) ? fr_w3[n * 64 + k] : 0.f);
    }
    __syncthreads();

    const int w = tid >> 5, lane = tid & 31;
    const int gid = lane >> 2, tig = lane & 3;
    uint16_t* actH = reinterpret_cast<uint16_t*>(smc + SM_WARP + w * WARP_BLK);
    uint16_t* actL = actH + 32 * APAD;
    float* dscr = reinterpret_cast<float*>(smc + SM_WARP + w * WARP_BLK);

    const int row = blockIdx.x * BLOCK + tid;
    const float* s = state + (size_t)row * 25;
    float* o = out + (size_t)row * 25;

    // ---------------- front (SIMT) ----------------
    float h0[13];
#pragma unroll
    for (int i = 0; i < 4; i++) { float v = s[i]; h0[i] = v; o[i] = v; }
#pragma unroll
    for (int i = 0; i < 9; i++) { float v = s[16 + i]; h0[4 + i] = v; o[16 + i] = v; }
    float hm8[8];
#pragma unroll
    for (int k = 0; k < 8; k++) {
        float a = scal[F_UH1B + k];
#pragma unroll
        for (int i = 0; i < 13; i++) a += h0[i] * scal[F_UH1W + k * 13 + i];
        hm8[k] = fmaxf(a, 0.f);
    }
    float gs = scal[F_G2B];
#pragma unroll
    for (int k = 0; k < 8; k++) {
        float a = scal[F_G1B + k];
#pragma unroll
        for (int i = 0; i < 8; i++) a += hm8[i] * scal[F_G1W + k * 8 + i];
        gs += fmaxf(a, 0.f) * scal[F_G2W + k];
    }
    float Zm0[8], Zm1[8], Zm2[8];
    {
        float Z0x[4], Z0y[4], Z0z[4];
#pragma unroll
        for (int j = 0; j < 4; j++) { Z0x[j] = s[4 + 3 * j]; Z0y[j] = s[5 + 3 * j]; Z0z[j] = s[6 + 3 * j]; }
        float Zu0[8], Zu1[8], Zu2[8];
#pragma unroll
        for (int k = 0; k < 8; k++) {
            float a0 = 0.f, a1 = 0.f, a2 = 0.f;
#pragma unroll
            for (int j = 0; j < 4; j++) {
                float wv = scal[F_UZ1 + k * 4 + j];
                a0 += Z0x[j] * wv; a1 += Z0y[j] * wv; a2 += Z0z[j] * wv;
            }
            Zu0[k] = a0; Zu1[k] = a1; Zu2[k] = a2;
        }
#pragma unroll
        for (int k = 0; k < 8; k++) {
            float a0 = 0.f, a1 = 0.f, a2 = 0.f;
#pragma unroll
            for (int m = 0; m < 8; m++) {
                float wv = scal[F_UZ2S + k * 8 + m];
                a0 += Zu0[m] * wv; a1 += Zu1[m] * wv; a2 += Zu2[m] * wv;
            }
            a2 += gs * scal[F_UZ2Z + k];
            Zm0[k] = a0; Zm1[k] = a1; Zm2[k] = a2;
        }
    }
    float xv[44], nrm = 0.f;
    {
        int p = 0;
#pragma unroll
        for (int a = 0; a < 8; a++)
#pragma unroll
            for (int b = a; b < 8; b++) {
                float v = Zm0[a] * Zm0[b] + Zm1[a] * Zm1[b] + Zm2[a] * Zm2[b];
                xv[p] = v;
                nrm += (a == b) ? v * v : 2.f * v * v;
                p++;
            }
    }
#pragma unroll
    for (int j = 0; j < 8; j++) xv[36 + j] = hm8[j];
    const float invFn = 1.f / (sqrtf(nrm) + 1.f);

    write_acts(actH, actL, lane, xv);
    __syncwarp();

    // ---------------- up_m chain: L1 -> L2 -> L3 (register-resident) ----------------
    float d1[2][8][4];
    layer_sm<3, 8>(actH, actL, d1, WT + WH_L1, WT + WL_L1, scal + F_B1, gid, tig);
    relu_d<8>(d1);
    float d2[2][8][4];
    layer_rr<4, 8>(d1, d2, WT + WH_L2, WT + WL_L2, scal + F_B2, gid, tig);
    relu_d<8>(d2);
    float d3[2][9][4];
    layer_rr<4, 9>(d2, d3, WT + WH_L3, WT + WL_L3, scal + F_B3, gid, tig);
    __syncwarp();              // acts reads done before D overwrites scratch
    store_D<9>(dscr, d3, gid, tig);
    __syncwarp();

    // ---------------- L3 post (row-coupled SIMT) ----------------
    float Yx[8], Yy[8], invFn2;
    {
        float rg[72];
#pragma unroll
        for (int i = 0; i < 72; i++) rg[i] = dscr[lane * DPAD + i];
        float uZ0[8], uZ1[8], uZ2[8], hm2[8];
#pragma unroll
        for (int k = 0; k < 8; k++) { uZ0[k] = 0.f; uZ1[k] = 0.f; uZ2[k] = 0.f; }
#pragma unroll
        for (int j = 0; j < 8; j++) {
#pragma unroll
            for (int k = 0; k < 8; k++) {
                float m = rg[j * 8 + k] * invFn;   // bias baked into acc init
                uZ0[k] += Zm0[j] * m; uZ1[k] += Zm1[j] * m; uZ2[k] += Zm2[j] * m;
            }
        }
#pragma unroll
        for (int j = 0; j < 8; j++)
            hm2[j] = fmaxf(rg[64 + j] * invFn, 0.f);
        float gs2 = scal[F_DG2B];
#pragma unroll
        for (int k = 0; k < 8; k++) {
            float a = scal[F_DG1B + k];
#pragma unroll
            for (int i = 0; i < 8; i++) a += hm2[i] * scal[F_DG1W + k * 8 + i];
            gs2 += fmaxf(a, 0.f) * scal[F_DG2W + k];
        }
        float Yz[8];
#pragma unroll
        for (int k = 0; k < 8; k++) {
            float a0 = 0.f, a1 = 0.f, a2 = 0.f;
#pragma unroll
            for (int j = 0; j < 8; j++) {
                float wv = scal[F_DZ2S + k * 8 + j];
                a0 += uZ0[j] * wv; a1 += uZ1[j] * wv; a2 += uZ2[j] * wv;
            }
            a2 += gs2 * scal[F_DZ2Z + k];
            Yx[k] = a0; Yy[k] = a1; Yz[k] = a2;
        }
        float nrm2 = 0.f;
        int p = 0;
#pragma unroll
        for (int a = 0; a < 8; a++)
#pragma unroll
            for (int b = a; b < 8; b++) {
                float v = Yx[a] * Yx[b] + Yy[a] * Yy[b] + Yz[a] * Yz[b];
                xv[p] = v;
                nrm2 += (a == b) ? v * v : 2.f * v * v;
                p++;
            }
#pragma unroll
        for (int j = 0; j < 8; j++) xv[36 + j] = hm2[j];
        invFn2 = 1.f / (sqrtf(nrm2) + 1.f);
    }
    __syncwarp();              // D reads done before acts overwrite
    write_acts(actH, actL, lane, xv);
    __syncwarp();

    // ---------------- fr chain: F1 -> F2 -> F3 ----------------
    float f1[2][8][4];
    layer_sm<3, 8>(actH, actL, f1, WT + WH_F1, WT + WL_F1, scal + F_FB1, gid, tig);
    relu_d<8>(f1);
    float f2[2][8][4];
    layer_rr<4, 8>(f1, f2, WT + WH_F2, WT + WL_F2, scal + F_FB2, gid, tig);
    relu_d<8>(f2);
    float f3[2][1][4];
    layer_rr<4, 1>(f2, f3, WT + WH_F3, WT + WL_F3, scal + F_FB3, gid, tig);
    __syncwarp();              // acts reads done before D overwrites
    store_D<1>(dscr, f3, gid, tig);
    __syncwarp();

    float frv[8];
#pragma unroll
    for (int k = 0; k < 8; k++) frv[k] = dscr[lane * DPAD + k] * invFn2;

    // ---------------- frame + rotation + writeback ----------------
    float fx = 0.f, fy = 0.f;
#pragma unroll
    for (int k = 0; k < 8; k++) { fx += Yx[k] * frv[k]; fy += Yy[k] * frv[k]; }
    const float nn = sqrtf(fx * fx + fy * fy) + 1e-6f;
    const float u1x = fx / nn, u1y = fy / nn;
#pragma unroll
    for (int j = 0; j < 4; j++) {
        const float zx = __ldg(&s[4 + 3 * j]);
        const float zy = __ldg(&s[5 + 3 * j]);
        const float zz = __ldg(&s[6 + 3 * j]);
        o[4 + 3 * j]     = u1x * zx + u1y * zy;
        o[4 + 3 * j + 1] = -u1y * zx + u1x * zy;
        o[4 + 3 * j + 2] = zz;
    }
}

extern "C" void kernel_launch(void* const* d_in, const int* in_sizes, int n_in,
                              void* d_out, int out_size) {
    (void)in_sizes; (void)n_in; (void)out_size;
    cudaFuncSetAttribute(frame_gnn_mma_kernel, cudaFuncAttributeMaxDynamicSharedMemorySize,
                         SMEM_BYTES);
    frame_gnn_mma_kernel<<<GRID, BLOCK, SMEM_BYTES>>>(
        (const float*)d_in[0],
        (const float*)d_in[1], (const float*)d_in[2], (const float*)d_in[3],
        (const float*)d_in[4], (const float*)d_in[5], (const float*)d_in[6], (const float*)d_in[7],
        (const float*)d_in[8],
        (const float*)d_in[9], (const float*)d_in[10], (const float*)d_in[11], (const float*)d_in[12],
        (const float*)d_in[13], (const float*)d_in[14],
        (const float*)d_in[15], (const float*)d_in[16], (const float*)d_in[17], (const float*)d_in[18],
        (const float*)d_in[19],
        (const float*)d_in[20], (const float*)d_in[21], (const float*)d_in[22], (const float*)d_in[23],
        (const float*)d_in[24], (const float*)d_in[25],
        (float*)d_out);
}

// round 10
// speedup vs baseline: 2.5039x; 1.1108x over previous
#include <cuda_runtime.h>
#include <cuda_bf16.h>
#include <cstdint>

#define BLOCK 384
#define NROWS 262144
#define GRID ((NROWS + BLOCK - 1) / BLOCK)   // 683

constexpr int KPAD = 72;   // weight k stride (bf16 elems) -> conflict-free B loads
constexpr int APAD = 56;   // acts col stride (bf16 elems) -> conflict-free A loads
constexpr int DPAD = 74;   // D scratch stride (f32 elems) -> 2-way conflicts only

// ---------------- scal float offsets ----------------
constexpr int F_UH1W=0, F_UH1B=104, F_G1W=112, F_G1B=176, F_G2W=184, F_G2B=192,
    F_UZ1=196, F_UZ2S=228, F_UZ2Z=292, F_DG1W=300, F_DG1B=364, F_DG2W=372,
    F_DG2B=380, F_DZ2S=384, F_DZ2Z=448, F_B1=456, F_B2=520, F_B3=584,
    F_FB1=656, F_FB2=720, F_FB3=784;   // 792 floats

// ---------------- smem layout ----------------
constexpr int SM_WT = 3584;                      // weights base (bytes)
constexpr int WH_L1=0,     WL_L1=4608,  WH_L2=9216,  WL_L2=13824,
              WH_L3=18432, WL_L3=23616, WH_F1=28800, WL_F1=33408,
              WH_F2=38016, WL_F2=42624, WH_F3=47232, WL_F3=47808;  // end 48384 elems
constexpr int SM_WARP  = SM_WT + 48384 * 2;      // 100352
constexpr int WARP_BLK = 9472;                   // per-warp scratch (acts 7168 / D 9472)
constexpr int NWARPS   = BLOCK / 32;             // 12
constexpr int SMEM_BYTES = SM_WARP + NWARPS * WARP_BLK;   // 214016

// gram pair index -> (a,b)
__device__ const unsigned char PA[36] = {0,0,0,0,0,0,0,0, 1,1,1,1,1,1,1, 2,2,2,2,2,2,
                                         3,3,3,3,3, 4,4,4,4, 5,5,5, 6,6, 7};
__device__ const unsigned char PB[36] = {0,1,2,3,4,5,6,7, 1,2,3,4,5,6,7, 2,3,4,5,6,7,
                                         3,4,5,6,7, 4,5,6,7, 5,6,7, 6,7, 7};

// ---------------- helpers ----------------
__device__ __forceinline__ void cvt2(float v0, float v1, uint32_t& hp, uint32_t& lp) {
    __nv_bfloat16 h0 = __float2bfloat16(v0), h1 = __float2bfloat16(v1);
    float r0 = v0 - __bfloat162float(h0), r1 = v1 - __bfloat162float(h1);
    __nv_bfloat16 l0 = __float2bfloat16(r0), l1 = __float2bfloat16(r1);
    __nv_bfloat162 hh; hh.x = h0; hh.y = h1;
    __nv_bfloat162 ll; ll.x = l0; ll.y = l1;
    hp = *reinterpret_cast<uint32_t*>(&hh);
    lp = *reinterpret_cast<uint32_t*>(&ll);
}

__device__ __forceinline__ void mma16816(float* d, const uint32_t* a, uint32_t b0, uint32_t b1) {
    asm volatile(
        "mma.sync.aligned.m16n8k16.row.col.f32.bf16.bf16.f32 "
        "{%0,%1,%2,%3}, {%4,%5,%6,%7}, {%8,%9}, {%0,%1,%2,%3};"
        : "+f"(d[0]), "+f"(d[1]), "+f"(d[2]), "+f"(d[3])
        : "r"(a[0]), "r"(a[1]), "r"(a[2]), "r"(a[3]), "r"(b0), "r"(b1));
}

// Layer with A from registers (previous D, bias+relu already applied).
template<int KT, int NT>
__device__ __forceinline__ void layer_rr(const float (&p)[2][2*KT][4], float (&dn)[2][NT][4],
                                         const uint16_t* WH, const uint16_t* WL,
                                         const float* bias, int gid, int tig) {
#pragma unroll
    for (int mt = 0; mt < 2; mt++)
#pragma unroll
        for (int nt = 0; nt < NT; nt++) {
            float2 b = *reinterpret_cast<const float2*>(bias + nt * 8 + 2 * tig);
            dn[mt][nt][0] = b.x; dn[mt][nt][1] = b.y;
            dn[mt][nt][2] = b.x; dn[mt][nt][3] = b.y;
        }
#pragma unroll
    for (int kt = 0; kt < KT; kt++) {
        uint32_t aH[2][4], aL[2][4];
#pragma unroll
        for (int mt = 0; mt < 2; mt++) {
            cvt2(p[mt][2*kt][0],   p[mt][2*kt][1],   aH[mt][0], aL[mt][0]);
            cvt2(p[mt][2*kt][2],   p[mt][2*kt][3],   aH[mt][1], aL[mt][1]);
            cvt2(p[mt][2*kt+1][0], p[mt][2*kt+1][1], aH[mt][2], aL[mt][2]);
            cvt2(p[mt][2*kt+1][2], p[mt][2*kt+1][3], aH[mt][3], aL[mt][3]);
        }
#pragma unroll
        for (int nt = 0; nt < NT; nt++) {
            const uint32_t* ph = reinterpret_cast<const uint32_t*>(WH + (nt*8+gid)*KPAD + kt*16 + 2*tig);
            const uint32_t* pl = reinterpret_cast<const uint32_t*>(WL + (nt*8+gid)*KPAD + kt*16 + 2*tig);
            uint32_t bh0 = ph[0], bh1 = ph[4], bl0 = pl[0], bl1 = pl[4];
#pragma unroll
            for (int mt = 0; mt < 2; mt++) {
                mma16816(dn[mt][nt], aH[mt], bh0, bh1);
                mma16816(dn[mt][nt], aH[mt], bl0, bl1);
                mma16816(dn[mt][nt], aL[mt], bh0, bh1);
            }
        }
    }
}

// Layer with A from smem acts (hi/lo planes, APAD stride).
template<int KT, int NT>
__device__ __forceinline__ void layer_sm(const uint16_t* actH, const uint16_t* actL,
                                         float (&dn)[2][NT][4],
                                         const uint16_t* WH, const uint16_t* WL,
                                         const float* bias, int gid, int tig) {
#pragma unroll
    for (int mt = 0; mt < 2; mt++)
#pragma unroll
        for (int nt = 0; nt < NT; nt++) {
            float2 b = *reinterpret_cast<const float2*>(bias + nt * 8 + 2 * tig);
            dn[mt][nt][0] = b.x; dn[mt][nt][1] = b.y;
            dn[mt][nt][2] = b.x; dn[mt][nt][3] = b.y;
        }
#pragma unroll
    for (int kt = 0; kt < KT; kt++) {
        uint32_t aH[2][4], aL[2][4];
#pragma unroll
        for (int mt = 0; mt < 2; mt++) {
            const int r0 = mt * 16 + gid, c0 = kt * 16 + 2 * tig;
            aH[mt][0] = *reinterpret_cast<const uint32_t*>(actH + r0 * APAD + c0);
            aH[mt][1] = *reinterpret_cast<const uint32_t*>(actH + (r0 + 8) * APAD + c0);
            aH[mt][2] = *reinterpret_cast<const uint32_t*>(actH + r0 * APAD + c0 + 8);
            aH[mt][3] = *reinterpret_cast<const uint32_t*>(actH + (r0 + 8) * APAD + c0 + 8);
            aL[mt][0] = *reinterpret_cast<const uint32_t*>(actL + r0 * APAD + c0);
            aL[mt][1] = *reinterpret_cast<const uint32_t*>(actL + (r0 + 8) * APAD + c0);
            aL[mt][2] = *reinterpret_cast<const uint32_t*>(actL + r0 * APAD + c0 + 8);
            aL[mt][3] = *reinterpret_cast<const uint32_t*>(actL + (r0 + 8) * APAD + c0 + 8);
        }
#pragma unroll
        for (int nt = 0; nt < NT; nt++) {
            const uint32_t* ph = reinterpret_cast<const uint32_t*>(WH + (nt*8+gid)*KPAD + kt*16 + 2*tig);
            const uint32_t* pl = reinterpret_cast<const uint32_t*>(WL + (nt*8+gid)*KPAD + kt*16 + 2*tig);
            uint32_t bh0 = ph[0], bh1 = ph[4], bl0 = pl[0], bl1 = pl[4];
#pragma unroll
            for (int mt = 0; mt < 2; mt++) {
                mma16816(dn[mt][nt], aH[mt], bh0, bh1);
                mma16816(dn[mt][nt], aH[mt], bl0, bl1);
                mma16816(dn[mt][nt], aL[mt], bh0, bh1);
            }
        }
    }
}

template<int NT>
__device__ __forceinline__ void relu_d(float (&d)[2][NT][4]) {
#pragma unroll
    for (int mt = 0; mt < 2; mt++)
#pragma unroll
        for (int nt = 0; nt < NT; nt++)
#pragma unroll
            for (int i = 0; i < 4; i++) d[mt][nt][i] = fmaxf(d[mt][nt][i], 0.f);
}

template<int NT>
__device__ __forceinline__ void store_D(float* dscr, const float (&d)[2][NT][4], int gid, int tig) {
#pragma unroll
    for (int mt = 0; mt < 2; mt++)
#pragma unroll
        for (int nt = 0; nt < NT; nt++) {
            *reinterpret_cast<float2*>(dscr + (mt*16+gid)*DPAD + nt*8 + 2*tig) =
                make_float2(d[mt][nt][0], d[mt][nt][1]);
            *reinterpret_cast<float2*>(dscr + (mt*16+gid+8)*DPAD + nt*8 + 2*tig) =
                make_float2(d[mt][nt][2], d[mt][nt][3]);
        }
}

__device__ __forceinline__ void write_acts(uint16_t* actH, uint16_t* actL, int lane, const float* xv) {
    uint32_t* ah = reinterpret_cast<uint32_t*>(actH + lane * APAD);
    uint32_t* al = reinterpret_cast<uint32_t*>(actL + lane * APAD);
#pragma unroll
    for (int c = 0; c < 48; c += 2) {
        float v0 = (c < 44) ? xv[c] : 0.f;
        float v1 = (c + 1 < 44) ? xv[c + 1] : 0.f;
        uint32_t hp, lp; cvt2(v0, v1, hp, lp);
        ah[c / 2] = hp; al[c / 2] = lp;
    }
}

__global__ void __launch_bounds__(BLOCK, 1) frame_gnn_mma_kernel(
    const float* __restrict__ state,
    const float* __restrict__ up_Z1_w, const float* __restrict__ up_h1_w, const float* __restrict__ up_h1_b,
    const float* __restrict__ up_g1_w1, const float* __restrict__ up_g1_b1,
    const float* __restrict__ up_g1_w2, const float* __restrict__ up_g1_b2,
    const float* __restrict__ up_Z2_w,
    const float* __restrict__ up_m_w1, const float* __restrict__ up_m_b1,
    const float* __restrict__ up_m_w2, const float* __restrict__ up_m_b2,
    const float* __restrict__ up_m_w3, const float* __restrict__ up_m_b3,
    const float* __restrict__ dn_g1_w1, const float* __restrict__ dn_g1_b1,
    const float* __restrict__ dn_g1_w2, const float* __restrict__ dn_g1_b2,
    const float* __restrict__ dn_Z2_w,
    const float* __restrict__ fr_w1, const float* __restrict__ fr_b1,
    const float* __restrict__ fr_w2, const float* __restrict__ fr_b2,
    const float* __restrict__ fr_w3, const float* __restrict__ fr_b3,
    float* __restrict__ out)
{
    extern __shared__ char smc[];
    float* scal = reinterpret_cast<float*>(smc);
    uint16_t* WT = reinterpret_cast<uint16_t*>(smc + SM_WT);
    const int tid = threadIdx.x;

    // ---------------- stage scalar weights ----------------
    for (int i = tid; i < 104; i += BLOCK) scal[F_UH1W + i] = up_h1_w[i];
    for (int i = tid; i < 32; i += BLOCK)  scal[F_UZ1 + i] = up_Z1_w[i];
    for (int i = tid; i < 64; i += BLOCK) {
        const int k = i >> 3, j = i & 7;
        scal[F_G1W + i]  = up_g1_w1[k * 24 + j];
        scal[F_DG1W + i] = dn_g1_w1[k * 16 + j];
        scal[F_UZ2S + i] = up_Z2_w[k * 25 + j];
        scal[F_DZ2S + i] = dn_Z2_w[k * 17 + j];
        scal[F_B1 + i] = up_m_b1[i];  scal[F_B2 + i] = up_m_b2[i];
        scal[F_FB1 + i] = fr_b1[i];   scal[F_FB2 + i] = fr_b2[i];
    }
    for (int i = tid; i < 72; i += BLOCK) scal[F_B3 + i] = up_m_b3[i];
    if (tid < 8) {
        scal[F_UH1B + tid] = up_h1_b[tid];
        scal[F_G1B + tid]  = up_g1_b1[tid];
        scal[F_G2W + tid]  = up_g1_w2[tid];
        scal[F_UZ2Z + tid] = up_Z2_w[tid * 25 + 24];
        scal[F_DG1B + tid] = dn_g1_b1[tid];
        scal[F_DG2W + tid] = dn_g1_w2[tid];
        scal[F_DZ2Z + tid] = dn_Z2_w[tid * 17 + 16];
        scal[F_FB3 + tid]  = fr_b3[tid];
    }
    if (tid == 0) { scal[F_G2B] = up_g1_b2[0]; scal[F_DG2B] = dn_g1_b2[0]; }

    // ---------------- stage weight matrices (bf16 split, [n][KPAD]) ----------------
    auto wsplit = [&](int offH, int offL, int idx, float v) {
        __nv_bfloat16 h = __float2bfloat16(v);
        __nv_bfloat16 l = __float2bfloat16(v - __bfloat162float(h));
        WT[offH + idx] = *reinterpret_cast<uint16_t*>(&h);
        WT[offL + idx] = *reinterpret_cast<uint16_t*>(&l);
    };
    for (int e = tid; e < 64 * KPAD; e += BLOCK) {   // L1 / F1 (folded gram)
        const int n = e / KPAD, k = e % KPAD;
        float v1 = 0.f, vf = 0.f;
        if (k < 36) {
            const int a = PA[k], b = PB[k];
            v1 = up_m_w1[n * 88 + a * 8 + b];
            vf = fr_w1[n * 80 + a * 8 + b];
            if (a != b) { v1 += up_m_w1[n * 88 + b * 8 + a]; vf += fr_w1[n * 80 + b * 8 + a]; }
        } else if (k < 44) {
            v1 = up_m_w1[n * 88 + 64 + (k - 36)];
            vf = fr_w1[n * 80 + 64 + (k - 36)];
        }
        wsplit(WH_L1, WL_L1, e, v1);
        wsplit(WH_F1, WL_F1, e, vf);
    }
    for (int e = tid; e < 64 * KPAD; e += BLOCK) {   // L2 / F2
        const int n = e / KPAD, k = e % KPAD;
        float v2 = (k < 64) ? up_m_w2[n * 64 + k] : 0.f;
        float vg = (k < 64) ? fr_w2[n * 64 + k] : 0.f;
        wsplit(WH_L2, WL_L2, e, v2);
        wsplit(WH_F2, WL_F2, e, vg);
    }
    for (int e = tid; e < 72 * KPAD; e += BLOCK) {   // L3
        const int n = e / KPAD, k = e % KPAD;
        wsplit(WH_L3, WL_L3, e, (k < 64) ? up_m_w3[n * 64 + k] : 0.f);
    }
    for (int e = tid; e < 8 * KPAD; e += BLOCK) {    // F3
        const int n = e / KPAD, k = e % KPAD;
        wsplit(WH_F3, WL_F3, e, (k < 64) ? fr_w3[n * 64 + k] : 0.f);
    }
    __syncthreads();

    const int w = tid >> 5, lane = tid & 31;
    const int gid = lane >> 2, tig = lane & 3;
    uint16_t* actH = reinterpret_cast<uint16_t*>(smc + SM_WARP + w * WARP_BLK);
    uint16_t* actL = actH + 32 * APAD;
    float* dscr = reinterpret_cast<float*>(smc + SM_WARP + w * WARP_BLK);

    // clamp row: duplicated tail rows compute identical values and write the
    // same bytes to the same addresses (deterministic, in-bounds)
    int row = blockIdx.x * BLOCK + tid;
    if (row >= NROWS) row = NROWS - 1;
    const float* s = state + (size_t)row * 25;
    float* o = out + (size_t)row * 25;

    // ---------------- front (SIMT) ----------------
    float h0[13];
#pragma unroll
    for (int i = 0; i < 4; i++) { float v = s[i]; h0[i] = v; o[i] = v; }
#pragma unroll
    for (int i = 0; i < 9; i++) { float v = s[16 + i]; h0[4 + i] = v; o[16 + i] = v; }
    float hm8[8];
#pragma unroll
    for (int k = 0; k < 8; k++) {
        float a = scal[F_UH1B + k];
#pragma unroll
        for (int i = 0; i < 13; i++) a += h0[i] * scal[F_UH1W + k * 13 + i];
        hm8[k] = fmaxf(a, 0.f);
    }
    float gs = scal[F_G2B];
#pragma unroll
    for (int k = 0; k < 8; k++) {
        float a = scal[F_G1B + k];
#pragma unroll
        for (int i = 0; i < 8; i++) a += hm8[i] * scal[F_G1W + k * 8 + i];
        gs += fmaxf(a, 0.f) * scal[F_G2W + k];
    }
    float Zm0[8], Zm1[8], Zm2[8];
    {
        float Z0x[4], Z0y[4], Z0z[4];
#pragma unroll
        for (int j = 0; j < 4; j++) { Z0x[j] = s[4 + 3 * j]; Z0y[j] = s[5 + 3 * j]; Z0z[j] = s[6 + 3 * j]; }
        float Zu0[8], Zu1[8], Zu2[8];
#pragma unroll
        for (int k = 0; k < 8; k++) {
            float a0 = 0.f, a1 = 0.f, a2 = 0.f;
#pragma unroll
            for (int j = 0; j < 4; j++) {
                float wv = scal[F_UZ1 + k * 4 + j];
                a0 += Z0x[j] * wv; a1 += Z0y[j] * wv; a2 += Z0z[j] * wv;
            }
            Zu0[k] = a0; Zu1[k] = a1; Zu2[k] = a2;
        }
#pragma unroll
        for (int k = 0; k < 8; k++) {
            float a0 = 0.f, a1 = 0.f, a2 = 0.f;
#pragma unroll
            for (int m = 0; m < 8; m++) {
                float wv = scal[F_UZ2S + k * 8 + m];
                a0 += Zu0[m] * wv; a1 += Zu1[m] * wv; a2 += Zu2[m] * wv;
            }
            a2 += gs * scal[F_UZ2Z + k];
            Zm0[k] = a0; Zm1[k] = a1; Zm2[k] = a2;
        }
    }
    float xv[44], nrm = 0.f;
    {
        int p = 0;
#pragma unroll
        for (int a = 0; a < 8; a++)
#pragma unroll
            for (int b = a; b < 8; b++) {
                float v = Zm0[a] * Zm0[b] + Zm1[a] * Zm1[b] + Zm2[a] * Zm2[b];
                xv[p] = v;
                nrm += (a == b) ? v * v : 2.f * v * v;
                p++;
            }
    }
#pragma unroll
    for (int j = 0; j < 8; j++) xv[36 + j] = hm8[j];
    const float invFn = 1.f / (sqrtf(nrm) + 1.f);

    write_acts(actH, actL, lane, xv);
    __syncwarp();

    // ---------------- up_m chain: L1 -> L2 -> L3 (register-resident) ----------------
    float d1[2][8][4];
    layer_sm<3, 8>(actH, actL, d1, WT + WH_L1, WT + WL_L1, scal + F_B1, gid, tig);
    relu_d<8>(d1);
    float d2[2][8][4];
    layer_rr<4, 8>(d1, d2, WT + WH_L2, WT + WL_L2, scal + F_B2, gid, tig);
    relu_d<8>(d2);
    float d3[2][9][4];
    layer_rr<4, 9>(d2, d3, WT + WH_L3, WT + WL_L3, scal + F_B3, gid, tig);
    __syncwarp();              // acts reads done before D overwrites scratch
    store_D<9>(dscr, d3, gid, tig);
    __syncwarp();

    // ---------------- L3 post (row-coupled SIMT) ----------------
    float Yx[8], Yy[8], invFn2;
    {
        float rg[72];
#pragma unroll
        for (int i = 0; i < 72; i++) rg[i] = dscr[lane * DPAD + i];
        float uZ0[8], uZ1[8], uZ2[8], hm2[8];
#pragma unroll
        for (int k = 0; k < 8; k++) { uZ0[k] = 0.f; uZ1[k] = 0.f; uZ2[k] = 0.f; }
#pragma unroll
        for (int j = 0; j < 8; j++) {
#pragma unroll
            for (int k = 0; k < 8; k++) {
                float m = rg[j * 8 + k] * invFn;   // bias baked into acc init
                uZ0[k] += Zm0[j] * m; uZ1[k] += Zm1[j] * m; uZ2[k] += Zm2[j] * m;
            }
        }
#pragma unroll
        for (int j = 0; j < 8; j++)
            hm2[j] = fmaxf(rg[64 + j] * invFn, 0.f);
        float gs2 = scal[F_DG2B];
#pragma unroll
        for (int k = 0; k < 8; k++) {
            float a = scal[F_DG1B + k];
#pragma unroll
            for (int i = 0; i < 8; i++) a += hm2[i] * scal[F_DG1W + k * 8 + i];
            gs2 += fmaxf(a, 0.f) * scal[F_DG2W + k];
        }
        float Yz[8];
#pragma unroll
        for (int k = 0; k < 8; k++) {
            float a0 = 0.f, a1 = 0.f, a2 = 0.f;
#pragma unroll
            for (int j = 0; j < 8; j++) {
                float wv = scal[F_DZ2S + k * 8 + j];
                a0 += uZ0[j] * wv; a1 += uZ1[j] * wv; a2 += uZ2[j] * wv;
            }
            a2 += gs2 * scal[F_DZ2Z + k];
            Yx[k] = a0; Yy[k] = a1; Yz[k] = a2;
        }
        float nrm2 = 0.f;
        int p = 0;
#pragma unroll
        for (int a = 0; a < 8; a++)
#pragma unroll
            for (int b = a; b < 8; b++) {
                float v = Yx[a] * Yx[b] + Yy[a] * Yy[b] + Yz[a] * Yz[b];
                xv[p] = v;
                nrm2 += (a == b) ? v * v : 2.f * v * v;
                p++;
            }
#pragma unroll
        for (int j = 0; j < 8; j++) xv[36 + j] = hm2[j];
        invFn2 = 1.f / (sqrtf(nrm2) + 1.f);
    }
    __syncwarp();              // D reads done before acts overwrite
    write_acts(actH, actL, lane, xv);
    __syncwarp();

    // ---------------- fr chain: F1 -> F2 -> F3 ----------------
    float f1[2][8][4];
    layer_sm<3, 8>(actH, actL, f1, WT + WH_F1, WT + WL_F1, scal + F_FB1, gid, tig);
    relu_d<8>(f1);
    float f2[2][8][4];
    layer_rr<4, 8>(f1, f2, WT + WH_F2, WT + WL_F2, scal + F_FB2, gid, tig);
    relu_d<8>(f2);
    float f3[2][1][4];
    layer_rr<4, 1>(f2, f3, WT + WH_F3, WT + WL_F3, scal + F_FB3, gid, tig);
    __syncwarp();              // acts reads done before D overwrites
    store_D<1>(dscr, f3, gid, tig);
    __syncwarp();

    float frv[8];
#pragma unroll
    for (int k = 0; k < 8; k++) frv[k] = dscr[lane * DPAD + k] * invFn2;

    // ---------------- frame + rotation + writeback ----------------
    float fx = 0.f, fy = 0.f;
#pragma unroll
    for (int k = 0; k < 8; k++) { fx += Yx[k] * frv[k]; fy += Yy[k] * frv[k]; }
    const float nn = sqrtf(fx * fx + fy * fy) + 1e-6f;
    const float u1x = fx / nn, u1y = fy / nn;
#pragma unroll
    for (int j = 0; j < 4; j++) {
        const float zx = __ldg(&s[4 + 3 * j]);
        const float zy = __ldg(&s[5 + 3 * j]);
        const float zz = __ldg(&s[6 + 3 * j]);
        o[4 + 3 * j]     = u1x * zx + u1y * zy;
        o[4 + 3 * j + 1] = -u1y * zx + u1x * zy;
        o[4 + 3 * j + 2] = zz;
    }
}

extern "C" void kernel_launch(void* const* d_in, const int* in_sizes, int n_in,
                              void* d_out, int out_size) {
    (void)in_sizes; (void)n_in; (void)out_size;
    cudaFuncSetAttribute(frame_gnn_mma_kernel, cudaFuncAttributeMaxDynamicSharedMemorySize,
                         SMEM_BYTES);
    frame_gnn_mma_kernel<<<GRID, BLOCK, SMEM_BYTES>>>(
        (const float*)d_in[0],
        (const float*)d_in[1], (const float*)d_in[2], (const float*)d_in[3],
        (const float*)d_in[4], (const float*)d_in[5], (const float*)d_in[6], (const float*)d_in[7],
        (const float*)d_in[8],
        (const float*)d_in[9], (const float*)d_in[10], (const float*)d_in[11], (const float*)d_in[12],
        (const float*)d_in[13], (const float*)d_in[14],
        (const float*)d_in[15], (const float*)d_in[16], (const float*)d_in[17], (const float*)d_in[18],
        (const float*)d_in[19],
        (const float*)d_in[20], (const float*)d_in[21], (const float*)d_in[22], (const float*)d_in[23],
        (const float*)d_in[24], (const float*)d_in[25],
        (float*)d_out);
}

// round 11
// speedup vs baseline: 3.2994x; 1.3177x over previous
#include <cuda_runtime.h>
#include <cuda_bf16.h>
#include <cstdint>

#define BLOCK 448
#define NROWS 262144
#define NBLKS ((NROWS + BLOCK - 1) / BLOCK)   // 586
#define GRID 148                               // persistent: 1 CTA/SM

constexpr int KPAD = 72;   // weight k stride (bf16) -> conflict-free B loads
constexpr int APAD = 56;   // acts col stride (bf16) -> conflict-free A loads
constexpr int DPAD = 73;   // D scratch stride (f32) -> conflict-free reads (gcd(9,32)=1)

// ---------------- scal float offsets ----------------
constexpr int F_UH1W=0, F_UH1B=104, F_G1W=112, F_G1B=176, F_G2W=184, F_G2B=192,
    F_UZ1=196, F_UZ2S=228, F_UZ2Z=292, F_DG1W=300, F_DG1B=364, F_DG2W=372,
    F_DG2B=380, F_DZ2S=384, F_DZ2Z=448, F_B1=456, F_B2=520, F_B3=584,
    F_FB1=656, F_FB2=720, F_FB3=784;   // 792 floats

// ---------------- smem layout ----------------
constexpr int SM_WT = 3584;                      // weights base (bytes)
constexpr int WH_L1=0,     WL_L1=4608,  WH_L2=9216,  WL_L2=13824,
              WH_L3=18432, WL_L3=23616, WH_F1=28800, WL_F1=33408,
              WH_F2=38016, WL_F2=42624, WH_F3=47232, WL_F3=47808;  // end 48384 elems
constexpr int SM_WARP  = SM_WT + 48384 * 2;      // 100352
constexpr int WARP_BLK = 32 * DPAD * 4;          // 9344 (acts 7168 overlays D region)
constexpr int NWARPS   = BLOCK / 32;             // 14
constexpr int SMEM_BYTES = SM_WARP + NWARPS * WARP_BLK;   // 231168

// gram pair index -> (a,b)
__device__ const unsigned char PA[36] = {0,0,0,0,0,0,0,0, 1,1,1,1,1,1,1, 2,2,2,2,2,2,
                                         3,3,3,3,3, 4,4,4,4, 5,5,5, 6,6, 7};
__device__ const unsigned char PB[36] = {0,1,2,3,4,5,6,7, 1,2,3,4,5,6,7, 2,3,4,5,6,7,
                                         3,4,5,6,7, 4,5,6,7, 5,6,7, 6,7, 7};

// ---------------- helpers ----------------
__device__ __forceinline__ void cvt2(float v0, float v1, uint32_t& hp, uint32_t& lp) {
    __nv_bfloat16 h0 = __float2bfloat16(v0), h1 = __float2bfloat16(v1);
    float r0 = v0 - __bfloat162float(h0), r1 = v1 - __bfloat162float(h1);
    __nv_bfloat16 l0 = __float2bfloat16(r0), l1 = __float2bfloat16(r1);
    __nv_bfloat162 hh; hh.x = h0; hh.y = h1;
    __nv_bfloat162 ll; ll.x = l0; ll.y = l1;
    hp = *reinterpret_cast<uint32_t*>(&hh);
    lp = *reinterpret_cast<uint32_t*>(&ll);
}

__device__ __forceinline__ void mma16816(float* d, const uint32_t* a, uint32_t b0, uint32_t b1) {
    asm volatile(
        "mma.sync.aligned.m16n8k16.row.col.f32.bf16.bf16.f32 "
        "{%0,%1,%2,%3}, {%4,%5,%6,%7}, {%8,%9}, {%0,%1,%2,%3};"
        : "+f"(d[0]), "+f"(d[1]), "+f"(d[2]), "+f"(d[3])
        : "r"(a[0]), "r"(a[1]), "r"(a[2]), "r"(a[3]), "r"(b0), "r"(b1));
}

// Layer with A from registers (previous D, bias+relu already applied).
template<int KT, int NT>
__device__ __forceinline__ void layer_rr(const float (&p)[2][2*KT][4], float (&dn)[2][NT][4],
                                         const uint16_t* WH, const uint16_t* WL,
                                         const float* bias, int gid, int tig) {
#pragma unroll
    for (int mt = 0; mt < 2; mt++)
#pragma unroll
        for (int nt = 0; nt < NT; nt++) {
            float2 b = *reinterpret_cast<const float2*>(bias + nt * 8 + 2 * tig);
            dn[mt][nt][0] = b.x; dn[mt][nt][1] = b.y;
            dn[mt][nt][2] = b.x; dn[mt][nt][3] = b.y;
        }
#pragma unroll
    for (int kt = 0; kt < KT; kt++) {
        uint32_t aH[2][4], aL[2][4];
#pragma unroll
        for (int mt = 0; mt < 2; mt++) {
            cvt2(p[mt][2*kt][0],   p[mt][2*kt][1],   aH[mt][0], aL[mt][0]);
            cvt2(p[mt][2*kt][2],   p[mt][2*kt][3],   aH[mt][1], aL[mt][1]);
            cvt2(p[mt][2*kt+1][0], p[mt][2*kt+1][1], aH[mt][2], aL[mt][2]);
            cvt2(p[mt][2*kt+1][2], p[mt][2*kt+1][3], aH[mt][3], aL[mt][3]);
        }
#pragma unroll
        for (int nt = 0; nt < NT; nt++) {
            const uint32_t* ph = reinterpret_cast<const uint32_t*>(WH + (nt*8+gid)*KPAD + kt*16 + 2*tig);
            const uint32_t* pl = reinterpret_cast<const uint32_t*>(WL + (nt*8+gid)*KPAD + kt*16 + 2*tig);
            uint32_t bh0 = ph[0], bh1 = ph[4], bl0 = pl[0], bl1 = pl[4];
#pragma unroll
            for (int mt = 0; mt < 2; mt++) {
                mma16816(dn[mt][nt], aH[mt], bh0, bh1);
                mma16816(dn[mt][nt], aH[mt], bl0, bl1);
                mma16816(dn[mt][nt], aL[mt], bh0, bh1);
            }
        }
    }
}

// Layer with A from smem acts (hi/lo planes, APAD stride).
template<int KT, int NT>
__device__ __forceinline__ void layer_sm(const uint16_t* actH, const uint16_t* actL,
                                         float (&dn)[2][NT][4],
                                         const uint16_t* WH, const uint16_t* WL,
                                         const float* bias, int gid, int tig) {
#pragma unroll
    for (int mt = 0; mt < 2; mt++)
#pragma unroll
        for (int nt = 0; nt < NT; nt++) {
            float2 b = *reinterpret_cast<const float2*>(bias + nt * 8 + 2 * tig);
            dn[mt][nt][0] = b.x; dn[mt][nt][1] = b.y;
            dn[mt][nt][2] = b.x; dn[mt][nt][3] = b.y;
        }
#pragma unroll
    for (int kt = 0; kt < KT; kt++) {
        uint32_t aH[2][4], aL[2][4];
#pragma unroll
        for (int mt = 0; mt < 2; mt++) {
            const int r0 = mt * 16 + gid, c0 = kt * 16 + 2 * tig;
            aH[mt][0] = *reinterpret_cast<const uint32_t*>(actH + r0 * APAD + c0);
            aH[mt][1] = *reinterpret_cast<const uint32_t*>(actH + (r0 + 8) * APAD + c0);
            aH[mt][2] = *reinterpret_cast<const uint32_t*>(actH + r0 * APAD + c0 + 8);
            aH[mt][3] = *reinterpret_cast<const uint32_t*>(actH + (r0 + 8) * APAD + c0 + 8);
            aL[mt][0] = *reinterpret_cast<const uint32_t*>(actL + r0 * APAD + c0);
            aL[mt][1] = *reinterpret_cast<const uint32_t*>(actL + (r0 + 8) * APAD + c0);
            aL[mt][2] = *reinterpret_cast<const uint32_t*>(actL + r0 * APAD + c0 + 8);
            aL[mt][3] = *reinterpret_cast<const uint32_t*>(actL + (r0 + 8) * APAD + c0 + 8);
        }
#pragma unroll
        for (int nt = 0; nt < NT; nt++) {
            const uint32_t* ph = reinterpret_cast<const uint32_t*>(WH + (nt*8+gid)*KPAD + kt*16 + 2*tig);
            const uint32_t* pl = reinterpret_cast<const uint32_t*>(WL + (nt*8+gid)*KPAD + kt*16 + 2*tig);
            uint32_t bh0 = ph[0], bh1 = ph[4], bl0 = pl[0], bl1 = pl[4];
#pragma unroll
            for (int mt = 0; mt < 2; mt++) {
                mma16816(dn[mt][nt], aH[mt], bh0, bh1);
                mma16816(dn[mt][nt], aH[mt], bl0, bl1);
                mma16816(dn[mt][nt], aL[mt], bh0, bh1);
            }
        }
    }
}

template<int NT>
__device__ __forceinline__ void relu_d(float (&d)[2][NT][4]) {
#pragma unroll
    for (int mt = 0; mt < 2; mt++)
#pragma unroll
        for (int nt = 0; nt < NT; nt++)
#pragma unroll
            for (int i = 0; i < 4; i++) d[mt][nt][i] = fmaxf(d[mt][nt][i], 0.f);
}

template<int NT>
__device__ __forceinline__ void store_D(float* dscr, const float (&d)[2][NT][4], int gid, int tig) {
#pragma unroll
    for (int mt = 0; mt < 2; mt++)
#pragma unroll
        for (int nt = 0; nt < NT; nt++) {
            dscr[(mt*16+gid)*DPAD + nt*8 + 2*tig]     = d[mt][nt][0];
            dscr[(mt*16+gid)*DPAD + nt*8 + 2*tig + 1] = d[mt][nt][1];
            dscr[(mt*16+gid+8)*DPAD + nt*8 + 2*tig]     = d[mt][nt][2];
            dscr[(mt*16+gid+8)*DPAD + nt*8 + 2*tig + 1] = d[mt][nt][3];
        }
}

__device__ __forceinline__ void write_acts(uint16_t* actH, uint16_t* actL, int lane, const float* xv) {
    uint32_t* ah = reinterpret_cast<uint32_t*>(actH + lane * APAD);
    uint32_t* al = reinterpret_cast<uint32_t*>(actL + lane * APAD);
#pragma unroll
    for (int c = 0; c < 48; c += 2) {
        float v0 = (c < 44) ? xv[c] : 0.f;
        float v1 = (c + 1 < 44) ? xv[c + 1] : 0.f;
        uint32_t hp, lp; cvt2(v0, v1, hp, lp);
        ah[c / 2] = hp; al[c / 2] = lp;
    }
}

__global__ void __launch_bounds__(BLOCK, 1) frame_gnn_mma_kernel(
    const float* __restrict__ state,
    const float* __restrict__ up_Z1_w, const float* __restrict__ up_h1_w, const float* __restrict__ up_h1_b,
    const float* __restrict__ up_g1_w1, const float* __restrict__ up_g1_b1,
    const float* __restrict__ up_g1_w2, const float* __restrict__ up_g1_b2,
    const float* __restrict__ up_Z2_w,
    const float* __restrict__ up_m_w1, const float* __restrict__ up_m_b1,
    const float* __restrict__ up_m_w2, const float* __restrict__ up_m_b2,
    const float* __restrict__ up_m_w3, const float* __restrict__ up_m_b3,
    const float* __restrict__ dn_g1_w1, const float* __restrict__ dn_g1_b1,
    const float* __restrict__ dn_g1_w2, const float* __restrict__ dn_g1_b2,
    const float* __restrict__ dn_Z2_w,
    const float* __restrict__ fr_w1, const float* __restrict__ fr_b1,
    const float* __restrict__ fr_w2, const float* __restrict__ fr_b2,
    const float* __restrict__ fr_w3, const float* __restrict__ fr_b3,
    float* __restrict__ out)
{
    extern __shared__ char smc[];
    float* scal = reinterpret_cast<float*>(smc);
    uint16_t* WT = reinterpret_cast<uint16_t*>(smc + SM_WT);
    const int tid = threadIdx.x;

    // ---------------- stage scalar weights (once) ----------------
    for (int i = tid; i < 104; i += BLOCK) scal[F_UH1W + i] = up_h1_w[i];
    for (int i = tid; i < 32; i += BLOCK)  scal[F_UZ1 + i] = up_Z1_w[i];
    for (int i = tid; i < 64; i += BLOCK) {
        const int k = i >> 3, j = i & 7;
        scal[F_G1W + i]  = up_g1_w1[k * 24 + j];
        scal[F_DG1W + i] = dn_g1_w1[k * 16 + j];
        scal[F_UZ2S + i] = up_Z2_w[k * 25 + j];
        scal[F_DZ2S + i] = dn_Z2_w[k * 17 + j];
        scal[F_B1 + i] = up_m_b1[i];  scal[F_B2 + i] = up_m_b2[i];
        scal[F_FB1 + i] = fr_b1[i];   scal[F_FB2 + i] = fr_b2[i];
    }
    for (int i = tid; i < 72; i += BLOCK) scal[F_B3 + i] = up_m_b3[i];
    if (tid < 8) {
        scal[F_UH1B + tid] = up_h1_b[tid];
        scal[F_G1B + tid]  = up_g1_b1[tid];
        scal[F_G2W + tid]  = up_g1_w2[tid];
        scal[F_UZ2Z + tid] = up_Z2_w[tid * 25 + 24];
        scal[F_DG1B + tid] = dn_g1_b1[tid];
        scal[F_DG2W + tid] = dn_g1_w2[tid];
        scal[F_DZ2Z + tid] = dn_Z2_w[tid * 17 + 16];
        scal[F_FB3 + tid]  = fr_b3[tid];
    }
    if (tid == 0) { scal[F_G2B] = up_g1_b2[0]; scal[F_DG2B] = dn_g1_b2[0]; }

    // ---------------- stage weight matrices (bf16 split, [n][KPAD], once) --------
    auto wsplit = [&](int offH, int offL, int idx, float v) {
        __nv_bfloat16 h = __float2bfloat16(v);
        __nv_bfloat16 l = __float2bfloat16(v - __bfloat162float(h));
        WT[offH + idx] = *reinterpret_cast<uint16_t*>(&h);
        WT[offL + idx] = *reinterpret_cast<uint16_t*>(&l);
    };
    for (int e = tid; e < 64 * KPAD; e += BLOCK) {   // L1 / F1 (folded gram)
        const int n = e / KPAD, k = e % KPAD;
        float v1 = 0.f, vf = 0.f;
        if (k < 36) {
            const int a = PA[k], b = PB[k];
            v1 = up_m_w1[n * 88 + a * 8 + b];
            vf = fr_w1[n * 80 + a * 8 + b];
            if (a != b) { v1 += up_m_w1[n * 88 + b * 8 + a]; vf += fr_w1[n * 80 + b * 8 + a]; }
        } else if (k < 44) {
            v1 = up_m_w1[n * 88 + 64 + (k - 36)];
            vf = fr_w1[n * 80 + 64 + (k - 36)];
        }
        wsplit(WH_L1, WL_L1, e, v1);
        wsplit(WH_F1, WL_F1, e, vf);
    }
    for (int e = tid; e < 64 * KPAD; e += BLOCK) {   // L2 / F2
        const int n = e / KPAD, k = e % KPAD;
        float v2 = (k < 64) ? up_m_w2[n * 64 + k] : 0.f;
        float vg = (k < 64) ? fr_w2[n * 64 + k] : 0.f;
        wsplit(WH_L2, WL_L2, e, v2);
        wsplit(WH_F2, WL_F2, e, vg);
    }
    for (int e = tid; e < 72 * KPAD; e += BLOCK) {   // L3
        const int n = e / KPAD, k = e % KPAD;
        wsplit(WH_L3, WL_L3, e, (k < 64) ? up_m_w3[n * 64 + k] : 0.f);
    }
    for (int e = tid; e < 8 * KPAD; e += BLOCK) {    // F3
        const int n = e / KPAD, k = e % KPAD;
        wsplit(WH_F3, WL_F3, e, (k < 64) ? fr_w3[n * 64 + k] : 0.f);
    }
    __syncthreads();

    const int w = tid >> 5, lane = tid & 31;
    const int gid = lane >> 2, tig = lane & 3;
    uint16_t* actH = reinterpret_cast<uint16_t*>(smc + SM_WARP + w * WARP_BLK);
    uint16_t* actL = actH + 32 * APAD;
    float* dscr = reinterpret_cast<float*>(smc + SM_WARP + w * WARP_BLK);

    // ---------------- persistent chunk loop (no cross-warp state) ----------------
    for (int blk = blockIdx.x; blk < NBLKS; blk += GRID) {
        int row = blk * BLOCK + tid;
        if (row >= NROWS) row = NROWS - 1;   // dup rows write identical values
        const float* s = state + (size_t)row * 25;
        float* o = out + (size_t)row * 25;

        // ---------------- front (SIMT) ----------------
        float h0[13];
#pragma unroll
        for (int i = 0; i < 4; i++) { float v = s[i]; h0[i] = v; o[i] = v; }
#pragma unroll
        for (int i = 0; i < 9; i++) { float v = s[16 + i]; h0[4 + i] = v; o[16 + i] = v; }
        float hm8[8];
#pragma unroll
        for (int k = 0; k < 8; k++) {
            float a = scal[F_UH1B + k];
#pragma unroll
            for (int i = 0; i < 13; i++) a += h0[i] * scal[F_UH1W + k * 13 + i];
            hm8[k] = fmaxf(a, 0.f);
        }
        float gs = scal[F_G2B];
#pragma unroll
        for (int k = 0; k < 8; k++) {
            float a = scal[F_G1B + k];
#pragma unroll
            for (int i = 0; i < 8; i++) a += hm8[i] * scal[F_G1W + k * 8 + i];
            gs += fmaxf(a, 0.f) * scal[F_G2W + k];
        }
        float Zm0[8], Zm1[8], Zm2[8];
        {
            float Z0x[4], Z0y[4], Z0z[4];
#pragma unroll
            for (int j = 0; j < 4; j++) { Z0x[j] = s[4 + 3 * j]; Z0y[j] = s[5 + 3 * j]; Z0z[j] = s[6 + 3 * j]; }
            float Zu0[8], Zu1[8], Zu2[8];
#pragma unroll
            for (int k = 0; k < 8; k++) {
                float a0 = 0.f, a1 = 0.f, a2 = 0.f;
#pragma unroll
                for (int j = 0; j < 4; j++) {
                    float wv = scal[F_UZ1 + k * 4 + j];
                    a0 += Z0x[j] * wv; a1 += Z0y[j] * wv; a2 += Z0z[j] * wv;
                }
                Zu0[k] = a0; Zu1[k] = a1; Zu2[k] = a2;
            }
#pragma unroll
            for (int k = 0; k < 8; k++) {
                float a0 = 0.f, a1 = 0.f, a2 = 0.f;
#pragma unroll
                for (int m = 0; m < 8; m++) {
                    float wv = scal[F_UZ2S + k * 8 + m];
                    a0 += Zu0[m] * wv; a1 += Zu1[m] * wv; a2 += Zu2[m] * wv;
                }
                a2 += gs * scal[F_UZ2Z + k];
                Zm0[k] = a0; Zm1[k] = a1; Zm2[k] = a2;
            }
        }
        float xv[44], nrm = 0.f;
        {
            int p = 0;
#pragma unroll
            for (int a = 0; a < 8; a++)
#pragma unroll
                for (int b = a; b < 8; b++) {
                    float v = Zm0[a] * Zm0[b] + Zm1[a] * Zm1[b] + Zm2[a] * Zm2[b];
                    xv[p] = v;
                    nrm += (a == b) ? v * v : 2.f * v * v;
                    p++;
                }
        }
#pragma unroll
        for (int j = 0; j < 8; j++) xv[36 + j] = hm8[j];
        const float invFn = 1.f / (sqrtf(nrm) + 1.f);

        write_acts(actH, actL, lane, xv);
        __syncwarp();

        // ---------------- up_m chain: L1 -> L2 -> L3 ----------------
        float d1[2][8][4];
        layer_sm<3, 8>(actH, actL, d1, WT + WH_L1, WT + WL_L1, scal + F_B1, gid, tig);
        relu_d<8>(d1);
        float d2[2][8][4];
        layer_rr<4, 8>(d1, d2, WT + WH_L2, WT + WL_L2, scal + F_B2, gid, tig);
        relu_d<8>(d2);
        float d3[2][9][4];
        layer_rr<4, 9>(d2, d3, WT + WH_L3, WT + WL_L3, scal + F_B3, gid, tig);
        __syncwarp();              // acts reads done before D overwrites scratch
        store_D<9>(dscr, d3, gid, tig);
        __syncwarp();

        // ---------------- L3 post (row-coupled SIMT) ----------------
        float Yx[8], Yy[8], invFn2;
        {
            float rg[72];
#pragma unroll
            for (int i = 0; i < 72; i++) rg[i] = dscr[lane * DPAD + i];
            float uZ0[8], uZ1[8], uZ2[8], hm2[8];
#pragma unroll
            for (int k = 0; k < 8; k++) { uZ0[k] = 0.f; uZ1[k] = 0.f; uZ2[k] = 0.f; }
#pragma unroll
            for (int j = 0; j < 8; j++) {
#pragma unroll
                for (int k = 0; k < 8; k++) {
                    float m = rg[j * 8 + k] * invFn;   // bias baked into acc init
                    uZ0[k] += Zm0[j] * m; uZ1[k] += Zm1[j] * m; uZ2[k] += Zm2[j] * m;
                }
            }
#pragma unroll
            for (int j = 0; j < 8; j++)
                hm2[j] = fmaxf(rg[64 + j] * invFn, 0.f);
            float gs2 = scal[F_DG2B];
#pragma unroll
            for (int k = 0; k < 8; k++) {
                float a = scal[F_DG1B + k];
#pragma unroll
                for (int i = 0; i < 8; i++) a += hm2[i] * scal[F_DG1W + k * 8 + i];
                gs2 += fmaxf(a, 0.f) * scal[F_DG2W + k];
            }
            float Yz[8];
#pragma unroll
            for (int k = 0; k < 8; k++) {
                float a0 = 0.f, a1 = 0.f, a2 = 0.f;
#pragma unroll
                for (int j = 0; j < 8; j++) {
                    float wv = scal[F_DZ2S + k * 8 + j];
                    a0 += uZ0[j] * wv; a1 += uZ1[j] * wv; a2 += uZ2[j] * wv;
                }
                a2 += gs2 * scal[F_DZ2Z + k];
                Yx[k] = a0; Yy[k] = a1; Yz[k] = a2;
            }
            float nrm2 = 0.f;
            int p = 0;
#pragma unroll
            for (int a = 0; a < 8; a++)
#pragma unroll
                for (int b = a; b < 8; b++) {
                    float v = Yx[a] * Yx[b] + Yy[a] * Yy[b] + Yz[a] * Yz[b];
                    xv[p] = v;
                    nrm2 += (a == b) ? v * v : 2.f * v * v;
                    p++;
                }
#pragma unroll
            for (int j = 0; j < 8; j++) xv[36 + j] = hm2[j];
            invFn2 = 1.f / (sqrtf(nrm2) + 1.f);
        }
        __syncwarp();              // D reads done before acts overwrite
        write_acts(actH, actL, lane, xv);
        __syncwarp();

        // ---------------- fr chain: F1 -> F2 -> F3 ----------------
        float f1[2][8][4];
        layer_sm<3, 8>(actH, actL, f1, WT + WH_F1, WT + WL_F1, scal + F_FB1, gid, tig);
        relu_d<8>(f1);
        float f2[2][8][4];
        layer_rr<4, 8>(f1, f2, WT + WH_F2, WT + WL_F2, scal + F_FB2, gid, tig);
        relu_d<8>(f2);
        float f3[2][1][4];
        layer_rr<4, 1>(f2, f3, WT + WH_F3, WT + WL_F3, scal + F_FB3, gid, tig);
        __syncwarp();              // acts reads done before D overwrites
        store_D<1>(dscr, f3, gid, tig);
        __syncwarp();

        float frv[8];
#pragma unroll
        for (int k = 0; k < 8; k++) frv[k] = dscr[lane * DPAD + k] * invFn2;

        // ---------------- frame + rotation + writeback ----------------
        float fx = 0.f, fy = 0.f;
#pragma unroll
        for (int k = 0; k < 8; k++) { fx += Yx[k] * frv[k]; fy += Yy[k] * frv[k]; }
        const float nn = sqrtf(fx * fx + fy * fy) + 1e-6f;
        const float u1x = fx / nn, u1y = fy / nn;
#pragma unroll
        for (int j = 0; j < 4; j++) {
            const float zx = __ldg(&s[4 + 3 * j]);
            const float zy = __ldg(&s[5 + 3 * j]);
            const float zz = __ldg(&s[6 + 3 * j]);
            o[4 + 3 * j]     = u1x * zx + u1y * zy;
            o[4 + 3 * j + 1] = -u1y * zx + u1x * zy;
            o[4 + 3 * j + 2] = zz;
        }
        __syncwarp();              // writeback reads of dscr done before next chunk's acts
    }
}

extern "C" void kernel_launch(void* const* d_in, const int* in_sizes, int n_in,
                              void* d_out, int out_size) {
    (void)in_sizes; (void)n_in; (void)out_size;
    cudaFuncSetAttribute(frame_gnn_mma_kernel, cudaFuncAttributeMaxDynamicSharedMemorySize,
                         SMEM_BYTES);
    frame_gnn_mma_kernel<<<GRID, BLOCK, SMEM_BYTES>>>(
        (const float*)d_in[0],
        (const float*)d_in[1], (const float*)d_in[2], (const float*)d_in[3],
        (const float*)d_in[4], (const float*)d_in[5], (const float*)d_in[6], (const float*)d_in[7],
        (const float*)d_in[8],
        (const float*)d_in[9], (const float*)d_in[10], (const float*)d_in[11], (const float*)d_in[12],
        (const float*)d_in[13], (const float*)d_in[14],
        (const float*)d_in[15], (const float*)d_in[16], (const float*)d_in[17], (const float*)d_in[18],
        (const float*)d_in[19],
        (const float*)d_in[20], (const float*)d_in[21], (const float*)d_in[22], (const float*)d_in[23],
        (const float*)d_in[24], (const float*)d_in[25],
        (float*)d_out);
}